// round 1
// baseline (speedup 1.0000x reference)
#include <cuda_runtime.h>
#include <math.h>

#define BB   2
#define SS   1024
#define DM   2048
#define NH   32
#define NKV  8
#define DK   64
#define MTOK (BB * SS)          // 2048 tokens
#define KVD  (NKV * DK)         // 512

// ---------------- scratch (device globals: no allocations allowed) ----------
__device__ float g_q[(size_t)MTOK * DM];                 // 16 MB
__device__ float g_k[(size_t)MTOK * KVD];                //  4 MB
__device__ float g_v[(size_t)MTOK * KVD];                //  4 MB
__device__ float g_attn[(size_t)MTOK * DM];              // 16 MB
__device__ float g_scores[(size_t)BB * NH * SS * SS];    // 256 MB

// ---------------- generic SGEMM + bias: C[M,N] = A[M,K] @ W[K,N] + bias -----
// 128x128 block tile, K-step 8, 256 threads, 8x8 microtile.
__global__ __launch_bounds__(256) void sgemm_bias_128(
    const float* __restrict__ A, const float* __restrict__ W,
    const float* __restrict__ bias, float* __restrict__ C,
    int Mdim, int Ndim, int Kdim)
{
    __shared__ float As[8][132];
    __shared__ float Bs[8][132];
    const int t  = threadIdx.x;
    const int tx = t & 15, ty = t >> 4;
    const int m0 = blockIdx.y * 128, n0 = blockIdx.x * 128;
    const int ar = t >> 1, ac = (t & 1) * 4;      // A: 128 rows x 8 k, one float4/thread
    const int bk = t >> 5, bn = (t & 31) * 4;     // B: 8 k x 128 cols, one float4/thread

    float acc[8][8];
#pragma unroll
    for (int i = 0; i < 8; i++)
#pragma unroll
        for (int j = 0; j < 8; j++) acc[i][j] = 0.f;

    const float* Aptr = A + (size_t)(m0 + ar) * Kdim + ac;
    for (int k0 = 0; k0 < Kdim; k0 += 8) {
        float4 av = *(const float4*)(Aptr + k0);
        As[ac + 0][ar] = av.x; As[ac + 1][ar] = av.y;
        As[ac + 2][ar] = av.z; As[ac + 3][ar] = av.w;
        float4 bv = *(const float4*)&W[(size_t)(k0 + bk) * Ndim + n0 + bn];
        *(float4*)&Bs[bk][bn] = bv;
        __syncthreads();
#pragma unroll
        for (int kk = 0; kk < 8; kk++) {
            float a[8], b[8];
            *(float4*)&a[0] = *(const float4*)&As[kk][ty * 8];
            *(float4*)&a[4] = *(const float4*)&As[kk][ty * 8 + 4];
            *(float4*)&b[0] = *(const float4*)&Bs[kk][tx * 8];
            *(float4*)&b[4] = *(const float4*)&Bs[kk][tx * 8 + 4];
#pragma unroll
            for (int i = 0; i < 8; i++)
#pragma unroll
                for (int j = 0; j < 8; j++)
                    acc[i][j] = fmaf(a[i], b[j], acc[i][j]);
        }
        __syncthreads();
    }
#pragma unroll
    for (int i = 0; i < 8; i++) {
        const int m = m0 + ty * 8 + i;
#pragma unroll
        for (int j = 0; j < 8; j++) {
            const int n = n0 + tx * 8 + j;
            C[(size_t)m * Ndim + n] = acc[i][j] + bias[n];
        }
    }
}

// ---------------- RoPE (in-place, interleaved even/odd pairs) ---------------
__global__ __launch_bounds__(256) void rope_kernel(float* __restrict__ t, int nheads)
{
    const int gid = blockIdx.x * blockDim.x + threadIdx.x;
    const int total = BB * SS * nheads * 32;
    if (gid >= total) return;
    const int i     = gid & 31;
    const int rest  = gid >> 5;
    const int h     = rest % nheads;
    const int token = rest / nheads;
    const int pos   = token % SS;
    const float inv = (float)pow(10000.0, -2.0 * (double)i / 64.0);
    const float ang = (float)pos * inv;
    float s, c;
    sincosf(ang, &s, &c);
    const size_t base = (size_t)token * (nheads * 64) + (size_t)h * 64 + 2 * i;
    const float te = t[base], to = t[base + 1];
    t[base]     = te * c - to * s;
    t[base + 1] = te * s + to * c;
}

// ---------------- scores: S[q,j] = (q_row . k_row) * 1/sqrt(64) -------------
// 64x64 tile per block; tiles fully above the diagonal are skipped entirely.
__global__ __launch_bounds__(256) void scores_kernel()
{
    const int jt = blockIdx.x, qt = blockIdx.y, bh = blockIdx.z;
    if (jt > qt) return;
    const int h = bh % NH, b = bh / NH, hk = h >> 2;
    __shared__ float Qs[64][68];
    __shared__ float Ks[64][68];
    const int t  = threadIdx.x;
    const int q0 = qt * 64, j0 = jt * 64;
#pragma unroll
    for (int u = 0; u < 16; u++) {
        const int idx = t + 256 * u;
        const int r = idx >> 6, d = idx & 63;
        Qs[d][r] = g_q[(size_t)(b * SS + q0 + r) * DM + h * 64 + d];
        Ks[d][r] = g_k[(size_t)(b * SS + j0 + r) * KVD + hk * 64 + d];
    }
    __syncthreads();
    const int tx = t & 15, ty = t >> 4;
    float acc[4][4];
#pragma unroll
    for (int i = 0; i < 4; i++)
#pragma unroll
        for (int j = 0; j < 4; j++) acc[i][j] = 0.f;
#pragma unroll 16
    for (int d = 0; d < 64; d++) {
        float a[4], bvec[4];
        *(float4*)a    = *(const float4*)&Qs[d][ty * 4];
        *(float4*)bvec = *(const float4*)&Ks[d][tx * 4];
#pragma unroll
        for (int i = 0; i < 4; i++)
#pragma unroll
            for (int j = 0; j < 4; j++)
                acc[i][j] = fmaf(a[i], bvec[j], acc[i][j]);
    }
    float* out = g_scores + ((size_t)bh * SS + q0) * SS + j0;
#pragma unroll
    for (int i = 0; i < 4; i++)
#pragma unroll
        for (int j = 0; j < 4; j++)
            out[(size_t)(ty * 4 + i) * SS + tx * 4 + j] = acc[i][j] * 0.125f;
}

// ---------------- causal row softmax (in place) -----------------------------
// Reads j in [0, q]; writes probs there and zeros up to the row's 64-tile end,
// so the PV kernel needs no masking.
__global__ __launch_bounds__(256) void softmax_kernel()
{
    const int row = blockIdx.x;          // 0 .. B*H*S-1
    const int q   = row % SS;
    float* p = g_scores + (size_t)row * SS;
    const int n = q + 1;
    const int t = threadIdx.x;
    __shared__ float red[256];

    float v[4];
    float mx = -INFINITY;
#pragma unroll
    for (int u = 0; u < 4; u++) {
        const int j = t + 256 * u;
        v[u] = (j < n) ? p[j] : -INFINITY;
        mx = fmaxf(mx, v[u]);
    }
    red[t] = mx; __syncthreads();
    for (int s2 = 128; s2 > 0; s2 >>= 1) {
        if (t < s2) red[t] = fmaxf(red[t], red[t + s2]);
        __syncthreads();
    }
    mx = red[0]; __syncthreads();

    float sum = 0.f;
#pragma unroll
    for (int u = 0; u < 4; u++) {
        const int j = t + 256 * u;
        v[u] = (j < n) ? __expf(v[u] - mx) : 0.f;
        sum += v[u];
    }
    red[t] = sum; __syncthreads();
    for (int s2 = 128; s2 > 0; s2 >>= 1) {
        if (t < s2) red[t] += red[t + s2];
        __syncthreads();
    }
    sum = red[0];

    const float inv = 1.0f / sum;
    const int nwrite = ((q >> 6) + 1) << 6;  // end of this row's diagonal tile
#pragma unroll
    for (int u = 0; u < 4; u++) {
        const int j = t + 256 * u;
        if (j < nwrite) p[j] = v[u] * inv;   // v[u]==0 for masked j
    }
}

// ---------------- PV: attn[q, h*64+d] = sum_j P[q,j] * V[j,d] ---------------
__global__ __launch_bounds__(256) void pv_kernel()
{
    const int qt = blockIdx.x, bh = blockIdx.z;
    const int h = bh % NH, b = bh / NH, hk = h >> 2;
    __shared__ float Ps[64][68];
    __shared__ float Vs[64][68];
    const int t  = threadIdx.x;
    const int tx = t & 15, ty = t >> 4;
    const int q0 = qt * 64;
    float acc[4][4];
#pragma unroll
    for (int i = 0; i < 4; i++)
#pragma unroll
        for (int j = 0; j < 4; j++) acc[i][j] = 0.f;

    for (int kt = 0; kt <= qt; kt++) {
        const int j0 = kt * 64;
#pragma unroll
        for (int u = 0; u < 16; u++) {
            const int idx = t + 256 * u;
            const int r = idx >> 6, c = idx & 63;
            Ps[c][r] = g_scores[((size_t)bh * SS + q0 + r) * SS + j0 + c];
            Vs[r][c] = g_v[(size_t)(b * SS + j0 + r) * KVD + hk * 64 + c];
        }
        __syncthreads();
#pragma unroll 16
        for (int kk = 0; kk < 64; kk++) {
            float a[4], bvec[4];
            *(float4*)a    = *(const float4*)&Ps[kk][ty * 4];
            *(float4*)bvec = *(const float4*)&Vs[kk][tx * 4];
#pragma unroll
            for (int i = 0; i < 4; i++)
#pragma unroll
                for (int j = 0; j < 4; j++)
                    acc[i][j] = fmaf(a[i], bvec[j], acc[i][j]);
        }
        __syncthreads();
    }
#pragma unroll
    for (int i = 0; i < 4; i++)
#pragma unroll
        for (int j = 0; j < 4; j++)
            g_attn[(size_t)(b * SS + q0 + ty * 4 + i) * DM + h * 64 + tx * 4 + j]
                = acc[i][j];
}

// ---------------- launch ----------------------------------------------------
extern "C" void kernel_launch(void* const* d_in, const int* in_sizes, int n_in,
                              void* d_out, int out_size)
{
    const float* x  = (const float*)d_in[0];
    const float* Wq = (const float*)d_in[1];
    const float* bq = (const float*)d_in[2];
    const float* Wk = (const float*)d_in[3];
    const float* bk = (const float*)d_in[4];
    const float* Wv = (const float*)d_in[5];
    const float* bv = (const float*)d_in[6];
    const float* Wo = (const float*)d_in[7];
    const float* bo = (const float*)d_in[8];
    float* out = (float*)d_out;

    float *q, *k, *v, *attn;
    cudaGetSymbolAddress((void**)&q,    g_q);
    cudaGetSymbolAddress((void**)&k,    g_k);
    cudaGetSymbolAddress((void**)&v,    g_v);
    cudaGetSymbolAddress((void**)&attn, g_attn);

    // Q/K/V projections
    sgemm_bias_128<<<dim3(DM / 128, MTOK / 128), 256>>>(x, Wq, bq, q, MTOK, DM, DM);
    sgemm_bias_128<<<dim3(KVD / 128, MTOK / 128), 256>>>(x, Wk, bk, k, MTOK, KVD, DM);
    sgemm_bias_128<<<dim3(KVD / 128, MTOK / 128), 256>>>(x, Wv, bv, v, MTOK, KVD, DM);

    // RoPE
    rope_kernel<<<(BB * SS * NH * 32) / 256, 256>>>(q, NH);
    rope_kernel<<<(BB * SS * NKV * 32) / 256, 256>>>(k, NKV);

    // attention
    scores_kernel<<<dim3(SS / 64, SS / 64, BB * NH), 256>>>();
    softmax_kernel<<<BB * NH * SS, 256>>>();
    pv_kernel<<<dim3(SS / 64, 1, BB * NH), 256>>>();

    // output projection
    sgemm_bias_128<<<dim3(DM / 128, MTOK / 128), 256>>>(attn, Wo, bo, out, MTOK, DM, DM);
}

// round 3
// speedup vs baseline: 2.5429x; 2.5429x over previous
#include <cuda_runtime.h>
#include <cstdint>
#include <math.h>

#define BB   2
#define SS   1024
#define DM   2048
#define NH   32
#define NKV  8
#define DK   64
#define MTOK (BB * SS)          // 2048 tokens
#define KVD  (NKV * DK)         // 512

// ---------------- scratch (device globals: no allocations allowed) ----------
__device__ float g_q[(size_t)MTOK * DM];                 // 16 MB
__device__ float g_k[(size_t)MTOK * KVD];                //  4 MB
__device__ float g_v[(size_t)MTOK * KVD];                //  4 MB
__device__ float g_attn[(size_t)MTOK * DM];              // 16 MB
__device__ float g_scores[(size_t)BB * NH * SS * SS];    // 256 MB

// ---------------- helpers ---------------------------------------------------
__device__ __forceinline__ uint32_t f2tf(float f) {
    uint32_t r;
    asm("cvt.rna.tf32.f32 %0, %1;" : "=r"(r) : "f"(f));
    return r;
}
__device__ __forceinline__ void mma16n8k8(float* c, const uint32_t* a,
                                          uint32_t b0, uint32_t b1) {
    asm volatile(
        "mma.sync.aligned.m16n8k8.row.col.f32.tf32.tf32.f32 "
        "{%0,%1,%2,%3}, {%4,%5,%6,%7}, {%8,%9}, {%0,%1,%2,%3};"
        : "+f"(c[0]), "+f"(c[1]), "+f"(c[2]), "+f"(c[3])
        : "r"(a[0]), "r"(a[1]), "r"(a[2]), "r"(a[3]), "r"(b0), "r"(b1));
}

// ============ tf32 mma.sync GEMM: C[M,N] = A[M,K] @ W[K,N] + bias ===========
// 128x128 CTA tile, BK=16, 256 threads, 8 warps (2m x 4n), 64x32 warp tile.
__global__ __launch_bounds__(256) void sgemm_mma(
    const float* __restrict__ A, const float* __restrict__ W,
    const float* __restrict__ bias, float* __restrict__ C,
    int Ndim, int Kdim)
{
    __shared__ uint32_t As[128][20];   // row-major, pad to 20 words
    __shared__ uint32_t Bs[16][136];   // k-major, pad to 136 words

    const int t    = threadIdx.x;
    const int wid  = t >> 5, lane = t & 31;
    const int g    = lane >> 2, tg = lane & 3;
    const int wm   = wid >> 2, wn = wid & 3;        // 2 x 4 warp grid
    const int m0   = blockIdx.y * 128, n0 = blockIdx.x * 128;

    // load indices (2 float4 per thread per tile)
    const int ar0 = t >> 2,  akc = (t & 3) * 4;     // A: rows t>>2, (t>>2)+64
    const int bk0 = t >> 5,  bcc = (t & 31) * 4;    // B: k rows t>>5, +8

    float acc[4][4][4];
#pragma unroll
    for (int i = 0; i < 4; i++)
#pragma unroll
        for (int j = 0; j < 4; j++)
#pragma unroll
            for (int r = 0; r < 4; r++) acc[i][j][r] = 0.f;

    // prefetch tile 0
    float4 av[2], bv[2];
    av[0] = *(const float4*)&A[(size_t)(m0 + ar0) * Kdim + akc];
    av[1] = *(const float4*)&A[(size_t)(m0 + ar0 + 64) * Kdim + akc];
    bv[0] = *(const float4*)&W[(size_t)bk0 * Ndim + n0 + bcc];
    bv[1] = *(const float4*)&W[(size_t)(bk0 + 8) * Ndim + n0 + bcc];

    const int NIT = Kdim >> 4;
    for (int it = 0; it < NIT; it++) {
        // store tf32-rounded tiles to SMEM
        *(uint4*)&As[ar0][akc]      = make_uint4(f2tf(av[0].x), f2tf(av[0].y),
                                                 f2tf(av[0].z), f2tf(av[0].w));
        *(uint4*)&As[ar0 + 64][akc] = make_uint4(f2tf(av[1].x), f2tf(av[1].y),
                                                 f2tf(av[1].z), f2tf(av[1].w));
        *(uint4*)&Bs[bk0][bcc]      = make_uint4(f2tf(bv[0].x), f2tf(bv[0].y),
                                                 f2tf(bv[0].z), f2tf(bv[0].w));
        *(uint4*)&Bs[bk0 + 8][bcc]  = make_uint4(f2tf(bv[1].x), f2tf(bv[1].y),
                                                 f2tf(bv[1].z), f2tf(bv[1].w));
        __syncthreads();

        // prefetch next tile (overlaps with compute below)
        if (it + 1 < NIT) {
            const int k0 = (it + 1) << 4;
            av[0] = *(const float4*)&A[(size_t)(m0 + ar0) * Kdim + k0 + akc];
            av[1] = *(const float4*)&A[(size_t)(m0 + ar0 + 64) * Kdim + k0 + akc];
            bv[0] = *(const float4*)&W[(size_t)(k0 + bk0) * Ndim + n0 + bcc];
            bv[1] = *(const float4*)&W[(size_t)(k0 + bk0 + 8) * Ndim + n0 + bcc];
        }

        // compute: 2 k-steps of 8, 16 mma each
#pragma unroll
        for (int ks = 0; ks < 16; ks += 8) {
            uint32_t afrag[4][4];
#pragma unroll
            for (int mf = 0; mf < 4; mf++) {
                const int row = wm * 64 + mf * 16 + g;
                afrag[mf][0] = As[row][ks + tg];
                afrag[mf][1] = As[row + 8][ks + tg];
                afrag[mf][2] = As[row][ks + tg + 4];
                afrag[mf][3] = As[row + 8][ks + tg + 4];
            }
#pragma unroll
            for (int nf = 0; nf < 4; nf++) {
                const int col = wn * 32 + nf * 8 + g;
                const uint32_t b0 = Bs[ks + tg][col];
                const uint32_t b1 = Bs[ks + tg + 4][col];
#pragma unroll
                for (int mf = 0; mf < 4; mf++)
                    mma16n8k8(acc[mf][nf], afrag[mf], b0, b1);
            }
        }
        __syncthreads();
    }

    // epilogue: acc + bias -> C (float2 stores)
#pragma unroll
    for (int mf = 0; mf < 4; mf++) {
        const int row = m0 + wm * 64 + mf * 16 + g;
#pragma unroll
        for (int nf = 0; nf < 4; nf++) {
            const int col = n0 + wn * 32 + nf * 8 + 2 * tg;
            const float bx = bias[col], by = bias[col + 1];
            *(float2*)&C[(size_t)row * Ndim + col] =
                make_float2(acc[mf][nf][0] + bx, acc[mf][nf][1] + by);
            *(float2*)&C[(size_t)(row + 8) * Ndim + col] =
                make_float2(acc[mf][nf][2] + bx, acc[mf][nf][3] + by);
        }
    }
}

// ---------------- RoPE (in-place, interleaved even/odd pairs) ---------------
__global__ __launch_bounds__(256) void rope_kernel(float* __restrict__ t, int nheads)
{
    const int gid = blockIdx.x * blockDim.x + threadIdx.x;
    const int total = BB * SS * nheads * 32;
    if (gid >= total) return;
    const int i     = gid & 31;
    const int rest  = gid >> 5;
    const int h     = rest % nheads;
    const int token = rest / nheads;
    const int pos   = token % SS;
    // inv_freq = 10000^(-i/32) = 2^(-log2(10000)/32 * i)
    const float inv = exp2f(-13.287712379549449f * (float)i * (1.0f / 32.0f));
    const float ang = (float)pos * inv;
    float s, c;
    sincosf(ang, &s, &c);
    const size_t base = (size_t)token * (nheads * 64) + (size_t)h * 64 + 2 * i;
    const float te = t[base], to = t[base + 1];
    t[base]     = te * c - to * s;
    t[base + 1] = te * s + to * c;
}

// ---------------- scores: S[q,j] = (q_row . k_row) * 1/sqrt(64) -------------
__global__ __launch_bounds__(256) void scores_kernel()
{
    const int jt = blockIdx.x, qt = blockIdx.y, bh = blockIdx.z;
    if (jt > qt) return;
    const int h = bh % NH, b = bh / NH, hk = h >> 2;
    __shared__ float Qs[64][68];
    __shared__ float Ks[64][68];
    const int t  = threadIdx.x;
    const int q0 = qt * 64, j0 = jt * 64;
#pragma unroll
    for (int u = 0; u < 16; u++) {
        const int idx = t + 256 * u;
        const int r = idx >> 6, d = idx & 63;
        Qs[d][r] = g_q[(size_t)(b * SS + q0 + r) * DM + h * 64 + d];
        Ks[d][r] = g_k[(size_t)(b * SS + j0 + r) * KVD + hk * 64 + d];
    }
    __syncthreads();
    const int tx = t & 15, ty = t >> 4;
    float acc[4][4];
#pragma unroll
    for (int i = 0; i < 4; i++)
#pragma unroll
        for (int j = 0; j < 4; j++) acc[i][j] = 0.f;
#pragma unroll 16
    for (int d = 0; d < 64; d++) {
        float a[4], bvec[4];
        *(float4*)a    = *(const float4*)&Qs[d][ty * 4];
        *(float4*)bvec = *(const float4*)&Ks[d][tx * 4];
#pragma unroll
        for (int i = 0; i < 4; i++)
#pragma unroll
            for (int j = 0; j < 4; j++)
                acc[i][j] = fmaf(a[i], bvec[j], acc[i][j]);
    }
    float* out = g_scores + ((size_t)bh * SS + q0) * SS + j0;
#pragma unroll
    for (int i = 0; i < 4; i++)
#pragma unroll
        for (int j = 0; j < 4; j++)
            out[(size_t)(ty * 4 + i) * SS + tx * 4 + j] = acc[i][j] * 0.125f;
}

// ---------------- causal row softmax (in place) -----------------------------
__global__ __launch_bounds__(256) void softmax_kernel()
{
    const int row = blockIdx.x;          // 0 .. B*H*S-1
    const int q   = row % SS;
    float* p = g_scores + (size_t)row * SS;
    const int n = q + 1;
    const int t = threadIdx.x;
    __shared__ float red[256];

    float v[4];
    float mx = -INFINITY;
#pragma unroll
    for (int u = 0; u < 4; u++) {
        const int j = t + 256 * u;
        v[u] = (j < n) ? p[j] : -INFINITY;
        mx = fmaxf(mx, v[u]);
    }
    red[t] = mx; __syncthreads();
    for (int s2 = 128; s2 > 0; s2 >>= 1) {
        if (t < s2) red[t] = fmaxf(red[t], red[t + s2]);
        __syncthreads();
    }
    mx = red[0]; __syncthreads();

    float sum = 0.f;
#pragma unroll
    for (int u = 0; u < 4; u++) {
        const int j = t + 256 * u;
        v[u] = (j < n) ? __expf(v[u] - mx) : 0.f;
        sum += v[u];
    }
    red[t] = sum; __syncthreads();
    for (int s2 = 128; s2 > 0; s2 >>= 1) {
        if (t < s2) red[t] += red[t + s2];
        __syncthreads();
    }
    sum = red[0];

    const float inv = 1.0f / sum;
    const int nwrite = ((q >> 6) + 1) << 6;  // end of this row's diagonal tile
#pragma unroll
    for (int u = 0; u < 4; u++) {
        const int j = t + 256 * u;
        if (j < nwrite) p[j] = v[u] * inv;   // v[u]==0 for masked j
    }
}

// ---------------- PV: attn[q, h*64+d] = sum_j P[q,j] * V[j,d] ---------------
__global__ __launch_bounds__(256) void pv_kernel()
{
    const int qt = blockIdx.x, bh = blockIdx.z;
    const int h = bh % NH, b = bh / NH, hk = h >> 2;
    __shared__ float Ps[64][68];
    __shared__ float Vs[64][68];
    const int t  = threadIdx.x;
    const int tx = t & 15, ty = t >> 4;
    const int q0 = qt * 64;
    float acc[4][4];
#pragma unroll
    for (int i = 0; i < 4; i++)
#pragma unroll
        for (int j = 0; j < 4; j++) acc[i][j] = 0.f;

    for (int kt = 0; kt <= qt; kt++) {
        const int j0 = kt * 64;
#pragma unroll
        for (int u = 0; u < 16; u++) {
            const int idx = t + 256 * u;
            const int r = idx >> 6, c = idx & 63;
            Ps[c][r] = g_scores[((size_t)bh * SS + q0 + r) * SS + j0 + c];
            Vs[r][c] = g_v[(size_t)(b * SS + j0 + r) * KVD + hk * 64 + c];
        }
        __syncthreads();
#pragma unroll 16
        for (int kk = 0; kk < 64; kk++) {
            float a[4], bvec[4];
            *(float4*)a    = *(const float4*)&Ps[kk][ty * 4];
            *(float4*)bvec = *(const float4*)&Vs[kk][tx * 4];
#pragma unroll
            for (int i = 0; i < 4; i++)
#pragma unroll
                for (int j = 0; j < 4; j++)
                    acc[i][j] = fmaf(a[i], bvec[j], acc[i][j]);
        }
        __syncthreads();
    }
#pragma unroll
    for (int i = 0; i < 4; i++)
#pragma unroll
        for (int j = 0; j < 4; j++)
            g_attn[(size_t)(b * SS + q0 + ty * 4 + i) * DM + h * 64 + tx * 4 + j]
                = acc[i][j];
}

// ---------------- launch ----------------------------------------------------
extern "C" void kernel_launch(void* const* d_in, const int* in_sizes, int n_in,
                              void* d_out, int out_size)
{
    const float* x  = (const float*)d_in[0];
    const float* Wq = (const float*)d_in[1];
    const float* bq = (const float*)d_in[2];
    const float* Wk = (const float*)d_in[3];
    const float* bk = (const float*)d_in[4];
    const float* Wv = (const float*)d_in[5];
    const float* bv = (const float*)d_in[6];
    const float* Wo = (const float*)d_in[7];
    const float* bo = (const float*)d_in[8];
    float* out = (float*)d_out;

    float *q, *k, *v, *attn;
    cudaGetSymbolAddress((void**)&q,    g_q);
    cudaGetSymbolAddress((void**)&k,    g_k);
    cudaGetSymbolAddress((void**)&v,    g_v);
    cudaGetSymbolAddress((void**)&attn, g_attn);

    // Q/K/V projections (tf32 mma.sync)
    sgemm_mma<<<dim3(DM / 128, MTOK / 128), 256>>>(x, Wq, bq, q, DM, DM);
    sgemm_mma<<<dim3(KVD / 128, MTOK / 128), 256>>>(x, Wk, bk, k, KVD, DM);
    sgemm_mma<<<dim3(KVD / 128, MTOK / 128), 256>>>(x, Wv, bv, v, KVD, DM);

    // RoPE
    rope_kernel<<<(BB * SS * NH * 32) / 256, 256>>>(q, NH);
    rope_kernel<<<(BB * SS * NKV * 32) / 256, 256>>>(k, NKV);

    // attention
    scores_kernel<<<dim3(SS / 64, SS / 64, BB * NH), 256>>>();
    softmax_kernel<<<BB * NH * SS, 256>>>();
    pv_kernel<<<dim3(SS / 64, 1, BB * NH), 256>>>();

    // output projection (tf32 mma.sync)
    sgemm_mma<<<dim3(DM / 128, MTOK / 128), 256>>>(attn, Wo, bo, out, DM, DM);
}

// round 5
// speedup vs baseline: 3.1821x; 1.2514x over previous
#include <cuda_runtime.h>
#include <cstdint>
#include <math.h>

#define BB   2
#define SS   1024
#define DM   2048
#define NH   32
#define NKV  8
#define DK   64
#define MTOK (BB * SS)          // 2048 tokens
#define KVD  (NKV * DK)         // 512
#define BQ   128
#define BJ   64

// ---------------- scratch (device globals: no allocations allowed) ----------
__device__ float g_q[(size_t)MTOK * DM];                 // 16 MB
__device__ float g_k[(size_t)MTOK * KVD];                //  4 MB
__device__ float g_v[(size_t)MTOK * KVD];                //  4 MB
__device__ float g_attn[(size_t)MTOK * DM];              // 16 MB

// ---------------- helpers ---------------------------------------------------
__device__ __forceinline__ uint32_t f2tf(float f) {
    uint32_t r;
    asm("cvt.rna.tf32.f32 %0, %1;" : "=r"(r) : "f"(f));
    return r;
}
__device__ __forceinline__ void mma16n8k8(float* c, const uint32_t* a,
                                          uint32_t b0, uint32_t b1) {
    asm volatile(
        "mma.sync.aligned.m16n8k8.row.col.f32.tf32.tf32.f32 "
        "{%0,%1,%2,%3}, {%4,%5,%6,%7}, {%8,%9}, {%0,%1,%2,%3};"
        : "+f"(c[0]), "+f"(c[1]), "+f"(c[2]), "+f"(c[3])
        : "r"(a[0]), "r"(a[1]), "r"(a[2]), "r"(a[3]), "r"(b0), "r"(b1));
}

// ============ tf32 mma.sync GEMM: C[M,N] = A[M,K] @ W[K,N] + bias ===========
// 128x128 CTA tile, BK=16, 256 threads, 8 warps (2m x 4n), 64x32 warp tile.
__global__ __launch_bounds__(256) void sgemm_mma(
    const float* __restrict__ A, const float* __restrict__ W,
    const float* __restrict__ bias, float* __restrict__ C,
    int Ndim, int Kdim)
{
    __shared__ uint32_t As[128][20];   // row-major, pad to 20 words
    __shared__ uint32_t Bs[16][136];   // k-major, pad to 136 words

    const int t    = threadIdx.x;
    const int wid  = t >> 5, lane = t & 31;
    const int g    = lane >> 2, tg = lane & 3;
    const int wm   = wid >> 2, wn = wid & 3;        // 2 x 4 warp grid
    const int m0   = blockIdx.y * 128, n0 = blockIdx.x * 128;

    const int ar0 = t >> 2,  akc = (t & 3) * 4;
    const int bk0 = t >> 5,  bcc = (t & 31) * 4;

    float acc[4][4][4];
#pragma unroll
    for (int i = 0; i < 4; i++)
#pragma unroll
        for (int j = 0; j < 4; j++)
#pragma unroll
            for (int r = 0; r < 4; r++) acc[i][j][r] = 0.f;

    float4 av[2], bv[2];
    av[0] = *(const float4*)&A[(size_t)(m0 + ar0) * Kdim + akc];
    av[1] = *(const float4*)&A[(size_t)(m0 + ar0 + 64) * Kdim + akc];
    bv[0] = *(const float4*)&W[(size_t)bk0 * Ndim + n0 + bcc];
    bv[1] = *(const float4*)&W[(size_t)(bk0 + 8) * Ndim + n0 + bcc];

    const int NIT = Kdim >> 4;
    for (int it = 0; it < NIT; it++) {
        *(uint4*)&As[ar0][akc]      = make_uint4(f2tf(av[0].x), f2tf(av[0].y),
                                                 f2tf(av[0].z), f2tf(av[0].w));
        *(uint4*)&As[ar0 + 64][akc] = make_uint4(f2tf(av[1].x), f2tf(av[1].y),
                                                 f2tf(av[1].z), f2tf(av[1].w));
        *(uint4*)&Bs[bk0][bcc]      = make_uint4(f2tf(bv[0].x), f2tf(bv[0].y),
                                                 f2tf(bv[0].z), f2tf(bv[0].w));
        *(uint4*)&Bs[bk0 + 8][bcc]  = make_uint4(f2tf(bv[1].x), f2tf(bv[1].y),
                                                 f2tf(bv[1].z), f2tf(bv[1].w));
        __syncthreads();

        if (it + 1 < NIT) {
            const int k0 = (it + 1) << 4;
            av[0] = *(const float4*)&A[(size_t)(m0 + ar0) * Kdim + k0 + akc];
            av[1] = *(const float4*)&A[(size_t)(m0 + ar0 + 64) * Kdim + k0 + akc];
            bv[0] = *(const float4*)&W[(size_t)(k0 + bk0) * Ndim + n0 + bcc];
            bv[1] = *(const float4*)&W[(size_t)(k0 + bk0 + 8) * Ndim + n0 + bcc];
        }

#pragma unroll
        for (int ks = 0; ks < 16; ks += 8) {
            uint32_t afrag[4][4];
#pragma unroll
            for (int mf = 0; mf < 4; mf++) {
                const int row = wm * 64 + mf * 16 + g;
                afrag[mf][0] = As[row][ks + tg];
                afrag[mf][1] = As[row + 8][ks + tg];
                afrag[mf][2] = As[row][ks + tg + 4];
                afrag[mf][3] = As[row + 8][ks + tg + 4];
            }
#pragma unroll
            for (int nf = 0; nf < 4; nf++) {
                const int col = wn * 32 + nf * 8 + g;
                const uint32_t b0 = Bs[ks + tg][col];
                const uint32_t b1 = Bs[ks + tg + 4][col];
#pragma unroll
                for (int mf = 0; mf < 4; mf++)
                    mma16n8k8(acc[mf][nf], afrag[mf], b0, b1);
            }
        }
        __syncthreads();
    }

#pragma unroll
    for (int mf = 0; mf < 4; mf++) {
        const int row = m0 + wm * 64 + mf * 16 + g;
#pragma unroll
        for (int nf = 0; nf < 4; nf++) {
            const int col = n0 + wn * 32 + nf * 8 + 2 * tg;
            const float bx = bias[col], by = bias[col + 1];
            *(float2*)&C[(size_t)row * Ndim + col] =
                make_float2(acc[mf][nf][0] + bx, acc[mf][nf][1] + by);
            *(float2*)&C[(size_t)(row + 8) * Ndim + col] =
                make_float2(acc[mf][nf][2] + bx, acc[mf][nf][3] + by);
        }
    }
}

// ---------------- RoPE (in-place, interleaved even/odd pairs) ---------------
__global__ __launch_bounds__(256) void rope_kernel(float* __restrict__ t, int nheads)
{
    const int gid = blockIdx.x * blockDim.x + threadIdx.x;
    const int total = BB * SS * nheads * 32;
    if (gid >= total) return;
    const int i     = gid & 31;
    const int rest  = gid >> 5;
    const int h     = rest % nheads;
    const int token = rest / nheads;
    const int pos   = token % SS;
    const float inv = exp2f(-13.287712379549449f * (float)i * (1.0f / 32.0f));
    const float ang = (float)pos * inv;
    float s, c;
    sincosf(ang, &s, &c);
    const size_t base = (size_t)token * (nheads * 64) + (size_t)h * 64 + 2 * i;
    const float te = t[base], to = t[base + 1];
    t[base]     = te * c - to * s;
    t[base + 1] = te * s + to * c;
}

// ============ fused flash attention (tf32 mma, online softmax) ==============
// CTA: 128 q-rows of one (b,h); 8 warps, each owns a 16-row strip.
__global__ __launch_bounds__(256, 2) void flash_kernel()
{
    __shared__ uint32_t Ks[64][65];    // K^T tile: [d][j]
    __shared__ uint32_t Vs[64][65];    // V tile:   [j][d]
    __shared__ uint32_t QPs[128][72];  // Q tile, then reused for P strips

    const int qt = blockIdx.x, bh = blockIdx.y;
    const int h = bh & (NH - 1), b = bh >> 5, hk = h >> 2;
    const int q0 = qt * BQ;
    const int t = threadIdx.x, w = t >> 5, lane = t & 31;
    const int g = lane >> 2, tg = lane & 3;
    const int r0 = w * 16 + g;

    // ---- stage Q tile (tf32) and pull fragments to registers ----
#pragma unroll
    for (int u = 0; u < 32; u++) {
        const int idx = t + 256 * u;               // 128*64 elems
        const int r = idx >> 6, d = idx & 63;
        QPs[r][d] = f2tf(g_q[(size_t)(b * SS + q0 + r) * DM + h * 64 + d]);
    }
    __syncthreads();
    uint32_t qf[8][4];
#pragma unroll
    for (int ks = 0; ks < 8; ks++) {
        qf[ks][0] = QPs[r0][ks * 8 + tg];
        qf[ks][1] = QPs[r0 + 8][ks * 8 + tg];
        qf[ks][2] = QPs[r0][ks * 8 + tg + 4];
        qf[ks][3] = QPs[r0 + 8][ks * 8 + tg + 4];
    }

    float o[8][4];
#pragma unroll
    for (int i = 0; i < 8; i++)
#pragma unroll
        for (int j = 0; j < 4; j++) o[i][j] = 0.f;
    float m0v = -INFINITY, m1v = -INFINITY, l0 = 0.f, l1 = 0.f;

    const int njt = 2 * qt + 2;
    for (int jt = 0; jt < njt; jt++) {
        const int j0 = jt * BJ;
        __syncthreads();                 // prev tile's K/V reads done
#pragma unroll
        for (int u = 0; u < 16; u++) {
            const int idx = t + 256 * u;           // 64*64 elems
            const int jj = idx >> 6, d = idx & 63;
            const size_t go = (size_t)(b * SS + j0 + jj) * KVD + hk * 64 + d;
            Ks[d][jj] = f2tf(g_k[go]);
            Vs[jj][d] = f2tf(g_v[go]);
        }
        __syncthreads();

        // ---- S = Q K^T ----
        float sf[8][4];
#pragma unroll
        for (int i = 0; i < 8; i++)
#pragma unroll
            for (int j = 0; j < 4; j++) sf[i][j] = 0.f;
#pragma unroll
        for (int ks = 0; ks < 8; ks++)
#pragma unroll
            for (int nf = 0; nf < 8; nf++) {
                const uint32_t b0 = Ks[ks * 8 + tg][nf * 8 + g];
                const uint32_t b1 = Ks[ks * 8 + tg + 4][nf * 8 + g];
                mma16n8k8(sf[nf], qf[ks], b0, b1);
            }

        // ---- causal mask (only tiles that can touch the diagonal) ----
        if (j0 + BJ - 1 > q0 + w * 16) {
            const int ra = q0 + r0, rb = ra + 8;
#pragma unroll
            for (int nf = 0; nf < 8; nf++) {
                const int c = j0 + nf * 8 + 2 * tg;
                if (c     > ra) sf[nf][0] = -INFINITY;
                if (c + 1 > ra) sf[nf][1] = -INFINITY;
                if (c     > rb) sf[nf][2] = -INFINITY;
                if (c + 1 > rb) sf[nf][3] = -INFINITY;
            }
        }

        // ---- online softmax ----
        float rm0 = -INFINITY, rm1 = -INFINITY;
#pragma unroll
        for (int nf = 0; nf < 8; nf++) {
            rm0 = fmaxf(rm0, fmaxf(sf[nf][0], sf[nf][1]));
            rm1 = fmaxf(rm1, fmaxf(sf[nf][2], sf[nf][3]));
        }
        rm0 = fmaxf(rm0, __shfl_xor_sync(0xffffffffu, rm0, 1));
        rm0 = fmaxf(rm0, __shfl_xor_sync(0xffffffffu, rm0, 2));
        rm1 = fmaxf(rm1, __shfl_xor_sync(0xffffffffu, rm1, 1));
        rm1 = fmaxf(rm1, __shfl_xor_sync(0xffffffffu, rm1, 2));

        const float mn0 = fmaxf(m0v, 0.125f * rm0);
        const float mn1 = fmaxf(m1v, 0.125f * rm1);
        const float a0 = __expf(m0v - mn0);
        const float a1 = __expf(m1v - mn1);
        m0v = mn0; m1v = mn1;

        float rs0 = 0.f, rs1 = 0.f;
#pragma unroll
        for (int nf = 0; nf < 8; nf++) {
            sf[nf][0] = __expf(fmaf(sf[nf][0], 0.125f, -mn0));
            sf[nf][1] = __expf(fmaf(sf[nf][1], 0.125f, -mn0));
            sf[nf][2] = __expf(fmaf(sf[nf][2], 0.125f, -mn1));
            sf[nf][3] = __expf(fmaf(sf[nf][3], 0.125f, -mn1));
            rs0 += sf[nf][0] + sf[nf][1];
            rs1 += sf[nf][2] + sf[nf][3];
        }
        rs0 += __shfl_xor_sync(0xffffffffu, rs0, 1);
        rs0 += __shfl_xor_sync(0xffffffffu, rs0, 2);
        rs1 += __shfl_xor_sync(0xffffffffu, rs1, 1);
        rs1 += __shfl_xor_sync(0xffffffffu, rs1, 2);
        l0 = l0 * a0 + rs0;
        l1 = l1 * a1 + rs1;

#pragma unroll
        for (int dn = 0; dn < 8; dn++) {
            o[dn][0] *= a0; o[dn][1] *= a0;
            o[dn][2] *= a1; o[dn][3] *= a1;
        }

        // ---- P -> SMEM (own strip; Q regs already extracted) ----
#pragma unroll
        for (int nf = 0; nf < 8; nf++) {
            const int c = nf * 8 + 2 * tg;
            QPs[r0][c]     = f2tf(sf[nf][0]);
            QPs[r0][c + 1] = f2tf(sf[nf][1]);
            QPs[r0 + 8][c]     = f2tf(sf[nf][2]);
            QPs[r0 + 8][c + 1] = f2tf(sf[nf][3]);
        }
        __syncwarp();

        // ---- O += P V ----
#pragma unroll
        for (int kb = 0; kb < 8; kb++) {
            uint32_t pa[4];
            pa[0] = QPs[r0][kb * 8 + tg];
            pa[1] = QPs[r0 + 8][kb * 8 + tg];
            pa[2] = QPs[r0][kb * 8 + tg + 4];
            pa[3] = QPs[r0 + 8][kb * 8 + tg + 4];
#pragma unroll
            for (int dn = 0; dn < 8; dn++) {
                const uint32_t b0 = Vs[kb * 8 + tg][dn * 8 + g];
                const uint32_t b1 = Vs[kb * 8 + tg + 4][dn * 8 + g];
                mma16n8k8(o[dn], pa, b0, b1);
            }
        }
    }

    // ---- epilogue: normalize, write ----
    const float il0 = 1.0f / l0, il1 = 1.0f / l1;
    const size_t ra = (size_t)(b * SS + q0 + r0) * DM + h * 64;
    const size_t rb = ra + (size_t)8 * DM;
#pragma unroll
    for (int dn = 0; dn < 8; dn++) {
        const int c = dn * 8 + 2 * tg;
        *(float2*)&g_attn[ra + c] = make_float2(o[dn][0] * il0, o[dn][1] * il0);
        *(float2*)&g_attn[rb + c] = make_float2(o[dn][2] * il1, o[dn][3] * il1);
    }
}

// ---------------- launch ----------------------------------------------------
extern "C" void kernel_launch(void* const* d_in, const int* in_sizes, int n_in,
                              void* d_out, int out_size)
{
    const float* x  = (const float*)d_in[0];
    const float* Wq = (const float*)d_in[1];
    const float* bq = (const float*)d_in[2];
    const float* Wk = (const float*)d_in[3];
    const float* bk = (const float*)d_in[4];
    const float* Wv = (const float*)d_in[5];
    const float* bv = (const float*)d_in[6];
    const float* Wo = (const float*)d_in[7];
    const float* bo = (const float*)d_in[8];
    float* out = (float*)d_out;

    float *q, *k, *v, *attn;
    cudaGetSymbolAddress((void**)&q,    g_q);
    cudaGetSymbolAddress((void**)&k,    g_k);
    cudaGetSymbolAddress((void**)&v,    g_v);
    cudaGetSymbolAddress((void**)&attn, g_attn);

    // Q/K/V projections (tf32 mma.sync)
    sgemm_mma<<<dim3(DM / 128, MTOK / 128), 256>>>(x, Wq, bq, q, DM, DM);
    sgemm_mma<<<dim3(KVD / 128, MTOK / 128), 256>>>(x, Wk, bk, k, KVD, DM);
    sgemm_mma<<<dim3(KVD / 128, MTOK / 128), 256>>>(x, Wv, bv, v, KVD, DM);

    // RoPE
    rope_kernel<<<(BB * SS * NH * 32) / 256, 256>>>(q, NH);
    rope_kernel<<<(BB * SS * NKV * 32) / 256, 256>>>(k, NKV);

    // fused attention
    flash_kernel<<<dim3(SS / BQ, BB * NH), 256>>>();

    // output projection (tf32 mma.sync)
    sgemm_mma<<<dim3(DM / 128, MTOK / 128), 256>>>(attn, Wo, bo, out, DM, DM);
}

// round 6
// speedup vs baseline: 3.1891x; 1.0022x over previous
#include <cuda_runtime.h>
#include <cstdint>
#include <math.h>

#define BB   2
#define SS   1024
#define DM   2048
#define NH   32
#define NKV  8
#define DK   64
#define MTOK (BB * SS)          // 2048 tokens
#define KVD  (NKV * DK)         // 512
#define BQ   128
#define BJ   64
#define STAGES 3

// ---------------- scratch (device globals: no allocations allowed) ----------
__device__ float g_q[(size_t)MTOK * DM];                 // 16 MB
__device__ float g_k[(size_t)MTOK * KVD];                //  4 MB
__device__ float g_v[(size_t)MTOK * KVD];                //  4 MB
__device__ float g_attn[(size_t)MTOK * DM];              // 16 MB

// ---------------- helpers ---------------------------------------------------
__device__ __forceinline__ uint32_t f2tf(float f) {
    uint32_t r;
    asm("cvt.rna.tf32.f32 %0, %1;" : "=r"(r) : "f"(f));
    return r;
}
__device__ __forceinline__ void mma16n8k8(float* c, const uint32_t* a,
                                          uint32_t b0, uint32_t b1) {
    asm volatile(
        "mma.sync.aligned.m16n8k8.row.col.f32.tf32.tf32.f32 "
        "{%0,%1,%2,%3}, {%4,%5,%6,%7}, {%8,%9}, {%0,%1,%2,%3};"
        : "+f"(c[0]), "+f"(c[1]), "+f"(c[2]), "+f"(c[3])
        : "r"(a[0]), "r"(a[1]), "r"(a[2]), "r"(a[3]), "r"(b0), "r"(b1));
}
__device__ __forceinline__ void cp16(void* smem, const void* g) {
    uint32_t s = (uint32_t)__cvta_generic_to_shared(smem);
    asm volatile("cp.async.cg.shared.global [%0], [%1], 16;" :: "r"(s), "l"(g));
}
#define CP_COMMIT() asm volatile("cp.async.commit_group;" ::: "memory")
#define CP_WAIT1()  asm volatile("cp.async.wait_group 1;" ::: "memory")

// ==== tf32 cp.async GEMM: C = A[M,K] @ W[K,N] + bias, optional fused RoPE ===
// 128x128 CTA tile, BK=16, 256 threads, 8 warps (2m x 4n), 3-stage pipeline.
__global__ __launch_bounds__(256) void sgemm_mma(
    const float* __restrict__ A, const float* __restrict__ W,
    const float* __restrict__ bias, float* __restrict__ C,
    int Ndim, int Kdim, int do_rope)
{
    __shared__ float As[STAGES][128][20];   // 128 rows x 16 k (+4 pad)
    __shared__ float Bs[STAGES][16][136];   // 16 k x 128 cols (+8 pad)

    const int t    = threadIdx.x;
    const int wid  = t >> 5, lane = t & 31;
    const int g    = lane >> 2, tg = lane & 3;
    const int wm   = wid >> 2, wn = wid & 3;        // 2 x 4 warp grid
    const int m0   = blockIdx.y * 128, n0 = blockIdx.x * 128;

    const int ar0 = t >> 2,  akc = (t & 3) * 4;
    const int bk0 = t >> 5,  bcc = (t & 31) * 4;

    float acc[4][4][4];
#pragma unroll
    for (int i = 0; i < 4; i++)
#pragma unroll
        for (int j = 0; j < 4; j++)
#pragma unroll
            for (int r = 0; r < 4; r++) acc[i][j][r] = 0.f;

    const int NIT = Kdim >> 4;

    // prologue: stages 0, 1
#pragma unroll
    for (int s = 0; s < 2; s++) {
        const int k0 = s << 4;
        cp16(&As[s][ar0][akc],      &A[(size_t)(m0 + ar0) * Kdim + k0 + akc]);
        cp16(&As[s][ar0 + 64][akc], &A[(size_t)(m0 + ar0 + 64) * Kdim + k0 + akc]);
        cp16(&Bs[s][bk0][bcc],      &W[(size_t)(k0 + bk0) * Ndim + n0 + bcc]);
        cp16(&Bs[s][bk0 + 8][bcc],  &W[(size_t)(k0 + bk0 + 8) * Ndim + n0 + bcc]);
        CP_COMMIT();
    }

    int sc = 0, sl = 2;                 // compute stage, load stage
    for (int it = 0; it < NIT; it++) {
        CP_WAIT1();
        __syncthreads();

        if (it + 2 < NIT) {
            const int k0 = (it + 2) << 4;
            cp16(&As[sl][ar0][akc],      &A[(size_t)(m0 + ar0) * Kdim + k0 + akc]);
            cp16(&As[sl][ar0 + 64][akc], &A[(size_t)(m0 + ar0 + 64) * Kdim + k0 + akc]);
            cp16(&Bs[sl][bk0][bcc],      &W[(size_t)(k0 + bk0) * Ndim + n0 + bcc]);
            cp16(&Bs[sl][bk0 + 8][bcc],  &W[(size_t)(k0 + bk0 + 8) * Ndim + n0 + bcc]);
        }
        CP_COMMIT();

#pragma unroll
        for (int ks = 0; ks < 16; ks += 8) {
            uint32_t afrag[4][4];
#pragma unroll
            for (int mf = 0; mf < 4; mf++) {
                const int row = wm * 64 + mf * 16 + g;
                afrag[mf][0] = f2tf(As[sc][row][ks + tg]);
                afrag[mf][1] = f2tf(As[sc][row + 8][ks + tg]);
                afrag[mf][2] = f2tf(As[sc][row][ks + tg + 4]);
                afrag[mf][3] = f2tf(As[sc][row + 8][ks + tg + 4]);
            }
#pragma unroll
            for (int nf = 0; nf < 4; nf++) {
                const int col = wn * 32 + nf * 8 + g;
                const uint32_t b0 = f2tf(Bs[sc][ks + tg][col]);
                const uint32_t b1 = f2tf(Bs[sc][ks + tg + 4][col]);
#pragma unroll
                for (int mf = 0; mf < 4; mf++)
                    mma16n8k8(acc[mf][nf], afrag[mf], b0, b1);
            }
        }
        sc = (sc + 1 == STAGES) ? 0 : sc + 1;
        sl = (sl + 1 == STAGES) ? 0 : sl + 1;
    }

    // epilogue: + bias, optional RoPE (thread owns adjacent even/odd cols)
#pragma unroll
    for (int mf = 0; mf < 4; mf++) {
        const int row = m0 + wm * 64 + mf * 16 + g;
#pragma unroll
        for (int nf = 0; nf < 4; nf++) {
            const int col = n0 + wn * 32 + nf * 8 + 2 * tg;
            const float bx = bias[col], by = bias[col + 1];
            float x0 = acc[mf][nf][0] + bx, x1 = acc[mf][nf][1] + by;
            float y0 = acc[mf][nf][2] + bx, y1 = acc[mf][nf][3] + by;
            if (do_rope) {
                const int i = (col & 63) >> 1;
                const float inv = exp2f(-13.287712379549449f * (float)i
                                        * (1.0f / 32.0f));
                float s0, c0, s1, c1;
                sincosf((float)(row & (SS - 1)) * inv, &s0, &c0);
                sincosf((float)((row + 8) & (SS - 1)) * inv, &s1, &c1);
                const float r0 = x0 * c0 - x1 * s0, r1 = x0 * s0 + x1 * c0;
                const float r2 = y0 * c1 - y1 * s1, r3 = y0 * s1 + y1 * c1;
                x0 = r0; x1 = r1; y0 = r2; y1 = r3;
            }
            *(float2*)&C[(size_t)row * Ndim + col]       = make_float2(x0, x1);
            *(float2*)&C[(size_t)(row + 8) * Ndim + col] = make_float2(y0, y1);
        }
    }
}

// ============ fused flash attention (tf32 mma, online softmax) ==============
// CTA: 128 q-rows of one (b,h); 8 warps, each owns a 16-row strip.
__global__ __launch_bounds__(256, 2) void flash_kernel()
{
    __shared__ uint32_t Ks[64][65];    // K^T tile: [d][j]
    __shared__ uint32_t Vs[64][65];    // V tile:   [j][d]
    __shared__ uint32_t QPs[128][72];  // Q tile, then reused for P strips

    const int qt = gridDim.x - 1 - blockIdx.x;   // biggest workloads first
    const int bh = blockIdx.y;
    const int h = bh & (NH - 1), b = bh >> 5, hk = h >> 2;
    const int q0 = qt * BQ;
    const int t = threadIdx.x, w = t >> 5, lane = t & 31;
    const int g = lane >> 2, tg = lane & 3;
    const int r0 = w * 16 + g;

    // ---- stage Q tile (tf32) and pull fragments to registers ----
#pragma unroll
    for (int u = 0; u < 32; u++) {
        const int idx = t + 256 * u;               // 128*64 elems
        const int r = idx >> 6, d = idx & 63;
        QPs[r][d] = f2tf(g_q[(size_t)(b * SS + q0 + r) * DM + h * 64 + d]);
    }
    __syncthreads();
    uint32_t qf[8][4];
#pragma unroll
    for (int ks = 0; ks < 8; ks++) {
        qf[ks][0] = QPs[r0][ks * 8 + tg];
        qf[ks][1] = QPs[r0 + 8][ks * 8 + tg];
        qf[ks][2] = QPs[r0][ks * 8 + tg + 4];
        qf[ks][3] = QPs[r0 + 8][ks * 8 + tg + 4];
    }

    float o[8][4];
#pragma unroll
    for (int i = 0; i < 8; i++)
#pragma unroll
        for (int j = 0; j < 4; j++) o[i][j] = 0.f;
    float m0v = -INFINITY, m1v = -INFINITY, l0 = 0.f, l1 = 0.f;

    const int njt = 2 * qt + 2;
    for (int jt = 0; jt < njt; jt++) {
        const int j0 = jt * BJ;
        __syncthreads();                 // prev tile's K/V reads done
#pragma unroll
        for (int u = 0; u < 16; u++) {
            const int idx = t + 256 * u;           // 64*64 elems
            const int jj = idx >> 6, d = idx & 63;
            const size_t go = (size_t)(b * SS + j0 + jj) * KVD + hk * 64 + d;
            Ks[d][jj] = f2tf(g_k[go]);
            Vs[jj][d] = f2tf(g_v[go]);
        }
        __syncthreads();

        // ---- S = Q K^T ----
        float sf[8][4];
#pragma unroll
        for (int i = 0; i < 8; i++)
#pragma unroll
            for (int j = 0; j < 4; j++) sf[i][j] = 0.f;
#pragma unroll
        for (int ks = 0; ks < 8; ks++)
#pragma unroll
            for (int nf = 0; nf < 8; nf++) {
                const uint32_t b0 = Ks[ks * 8 + tg][nf * 8 + g];
                const uint32_t b1 = Ks[ks * 8 + tg + 4][nf * 8 + g];
                mma16n8k8(sf[nf], qf[ks], b0, b1);
            }

        // ---- causal mask (only tiles that can touch the diagonal) ----
        if (j0 + BJ - 1 > q0 + w * 16) {
            const int ra = q0 + r0, rb = ra + 8;
#pragma unroll
            for (int nf = 0; nf < 8; nf++) {
                const int c = j0 + nf * 8 + 2 * tg;
                if (c     > ra) sf[nf][0] = -INFINITY;
                if (c + 1 > ra) sf[nf][1] = -INFINITY;
                if (c     > rb) sf[nf][2] = -INFINITY;
                if (c + 1 > rb) sf[nf][3] = -INFINITY;
            }
        }

        // ---- online softmax ----
        float rm0 = -INFINITY, rm1 = -INFINITY;
#pragma unroll
        for (int nf = 0; nf < 8; nf++) {
            rm0 = fmaxf(rm0, fmaxf(sf[nf][0], sf[nf][1]));
            rm1 = fmaxf(rm1, fmaxf(sf[nf][2], sf[nf][3]));
        }
        rm0 = fmaxf(rm0, __shfl_xor_sync(0xffffffffu, rm0, 1));
        rm0 = fmaxf(rm0, __shfl_xor_sync(0xffffffffu, rm0, 2));
        rm1 = fmaxf(rm1, __shfl_xor_sync(0xffffffffu, rm1, 1));
        rm1 = fmaxf(rm1, __shfl_xor_sync(0xffffffffu, rm1, 2));

        const float mn0 = fmaxf(m0v, 0.125f * rm0);
        const float mn1 = fmaxf(m1v, 0.125f * rm1);
        const float a0 = __expf(m0v - mn0);
        const float a1 = __expf(m1v - mn1);
        m0v = mn0; m1v = mn1;

        float rs0 = 0.f, rs1 = 0.f;
#pragma unroll
        for (int nf = 0; nf < 8; nf++) {
            sf[nf][0] = __expf(fmaf(sf[nf][0], 0.125f, -mn0));
            sf[nf][1] = __expf(fmaf(sf[nf][1], 0.125f, -mn0));
            sf[nf][2] = __expf(fmaf(sf[nf][2], 0.125f, -mn1));
            sf[nf][3] = __expf(fmaf(sf[nf][3], 0.125f, -mn1));
            rs0 += sf[nf][0] + sf[nf][1];
            rs1 += sf[nf][2] + sf[nf][3];
        }
        rs0 += __shfl_xor_sync(0xffffffffu, rs0, 1);
        rs0 += __shfl_xor_sync(0xffffffffu, rs0, 2);
        rs1 += __shfl_xor_sync(0xffffffffu, rs1, 1);
        rs1 += __shfl_xor_sync(0xffffffffu, rs1, 2);
        l0 = l0 * a0 + rs0;
        l1 = l1 * a1 + rs1;

#pragma unroll
        for (int dn = 0; dn < 8; dn++) {
            o[dn][0] *= a0; o[dn][1] *= a0;
            o[dn][2] *= a1; o[dn][3] *= a1;
        }

        // ---- P -> SMEM (own strip; Q regs already extracted) ----
#pragma unroll
        for (int nf = 0; nf < 8; nf++) {
            const int c = nf * 8 + 2 * tg;
            QPs[r0][c]     = f2tf(sf[nf][0]);
            QPs[r0][c + 1] = f2tf(sf[nf][1]);
            QPs[r0 + 8][c]     = f2tf(sf[nf][2]);
            QPs[r0 + 8][c + 1] = f2tf(sf[nf][3]);
        }
        __syncwarp();

        // ---- O += P V ----
#pragma unroll
        for (int kb = 0; kb < 8; kb++) {
            uint32_t pa[4];
            pa[0] = QPs[r0][kb * 8 + tg];
            pa[1] = QPs[r0 + 8][kb * 8 + tg];
            pa[2] = QPs[r0][kb * 8 + tg + 4];
            pa[3] = QPs[r0 + 8][kb * 8 + tg + 4];
#pragma unroll
            for (int dn = 0; dn < 8; dn++) {
                const uint32_t b0 = Vs[kb * 8 + tg][dn * 8 + g];
                const uint32_t b1 = Vs[kb * 8 + tg + 4][dn * 8 + g];
                mma16n8k8(o[dn], pa, b0, b1);
            }
        }
    }

    // ---- epilogue: normalize, write ----
    const float il0 = 1.0f / l0, il1 = 1.0f / l1;
    const size_t ra = (size_t)(b * SS + q0 + r0) * DM + h * 64;
    const size_t rb = ra + (size_t)8 * DM;
#pragma unroll
    for (int dn = 0; dn < 8; dn++) {
        const int c = dn * 8 + 2 * tg;
        *(float2*)&g_attn[ra + c] = make_float2(o[dn][0] * il0, o[dn][1] * il0);
        *(float2*)&g_attn[rb + c] = make_float2(o[dn][2] * il1, o[dn][3] * il1);
    }
}

// ---------------- launch ----------------------------------------------------
extern "C" void kernel_launch(void* const* d_in, const int* in_sizes, int n_in,
                              void* d_out, int out_size)
{
    const float* x  = (const float*)d_in[0];
    const float* Wq = (const float*)d_in[1];
    const float* bq = (const float*)d_in[2];
    const float* Wk = (const float*)d_in[3];
    const float* bk = (const float*)d_in[4];
    const float* Wv = (const float*)d_in[5];
    const float* bv = (const float*)d_in[6];
    const float* Wo = (const float*)d_in[7];
    const float* bo = (const float*)d_in[8];
    float* out = (float*)d_out;

    float *q, *k, *v, *attn;
    cudaGetSymbolAddress((void**)&q,    g_q);
    cudaGetSymbolAddress((void**)&k,    g_k);
    cudaGetSymbolAddress((void**)&v,    g_v);
    cudaGetSymbolAddress((void**)&attn, g_attn);

    // Q/K/V projections (tf32 mma.sync, RoPE fused into Q/K epilogues)
    sgemm_mma<<<dim3(DM / 128, MTOK / 128), 256>>>(x, Wq, bq, q, DM, DM, 1);
    sgemm_mma<<<dim3(KVD / 128, MTOK / 128), 256>>>(x, Wk, bk, k, KVD, DM, 1);
    sgemm_mma<<<dim3(KVD / 128, MTOK / 128), 256>>>(x, Wv, bv, v, KVD, DM, 0);

    // fused attention
    flash_kernel<<<dim3(SS / BQ, BB * NH), 256>>>();

    // output projection (tf32 mma.sync)
    sgemm_mma<<<dim3(DM / 128, MTOK / 128), 256>>>(attn, Wo, bo, out, DM, DM, 0);
}

// round 7
// speedup vs baseline: 4.2495x; 1.3325x over previous
#include <cuda_runtime.h>
#include <cstdint>
#include <math.h>

#define BB   2
#define SS   1024
#define DM   2048
#define NH   32
#define NKV  8
#define DK   64
#define MTOK (BB * SS)          // 2048 tokens
#define KVD  (NKV * DK)         // 512
#define BQ   128
#define BJ   64
#define STAGES 3

// ---------------- scratch (device globals: no allocations allowed) ----------
__device__ float g_q[(size_t)MTOK * DM];
__device__ float g_k[(size_t)MTOK * KVD];
__device__ float g_v[(size_t)MTOK * KVD];
__device__ float g_attn[(size_t)MTOK * DM];
__device__ float g_xr[(size_t)MTOK * DM];    // tf32-rounded x
__device__ float g_wq[(size_t)DM * DM];
__device__ float g_wk[(size_t)DM * KVD];
__device__ float g_wv[(size_t)DM * KVD];
__device__ float g_wo[(size_t)DM * DM];

// ---------------- helpers ---------------------------------------------------
__device__ __forceinline__ uint32_t f2tf(float f) {
    uint32_t r;
    asm("cvt.rna.tf32.f32 %0, %1;" : "=r"(r) : "f"(f));
    return r;
}
__device__ __forceinline__ void mma16n8k8(float* c, const uint32_t* a,
                                          uint32_t b0, uint32_t b1) {
    asm volatile(
        "mma.sync.aligned.m16n8k8.row.col.f32.tf32.tf32.f32 "
        "{%0,%1,%2,%3}, {%4,%5,%6,%7}, {%8,%9}, {%0,%1,%2,%3};"
        : "+f"(c[0]), "+f"(c[1]), "+f"(c[2]), "+f"(c[3])
        : "r"(a[0]), "r"(a[1]), "r"(a[2]), "r"(a[3]), "r"(b0), "r"(b1));
}
__device__ __forceinline__ void cp16(void* smem, const void* g) {
    uint32_t s = (uint32_t)__cvta_generic_to_shared(smem);
    asm volatile("cp.async.cg.shared.global [%0], [%1], 16;" :: "r"(s), "l"(g));
}
#define CP_COMMIT() asm volatile("cp.async.commit_group;" ::: "memory")
#define CP_WAIT1()  asm volatile("cp.async.wait_group 1;" ::: "memory")
#define CP_WAIT0()  asm volatile("cp.async.wait_group 0;" ::: "memory")

// ---------------- tf32 pre-round (elementwise, float4) ----------------------
__global__ __launch_bounds__(256) void tf32_round_kernel(
    const float* __restrict__ s, float* __restrict__ d, int n4)
{
    const int i = blockIdx.x * blockDim.x + threadIdx.x;
    if (i >= n4) return;
    float4 v = ((const float4*)s)[i];
    ((uint4*)d)[i] = make_uint4(f2tf(v.x), f2tf(v.y), f2tf(v.z), f2tf(v.w));
}

// ==== tf32 GEMM (pre-rounded inputs): C = A @ W + bias, opt RoPE/round ======
// 128x128 CTA tile, BK=16, 256 threads, 8 warps (2m x 4n), 3-stage cp.async.
__global__ __launch_bounds__(256) void sgemm_mma(
    const float* __restrict__ A, const float* __restrict__ W,
    const float* __restrict__ bias, float* __restrict__ C,
    int Ndim, int Kdim, int do_rope, int round_out)
{
    __shared__ float As[STAGES][128][20];
    __shared__ float Bs[STAGES][16][136];

    const int t    = threadIdx.x;
    const int wid  = t >> 5, lane = t & 31;
    const int g    = lane >> 2, tg = lane & 3;
    const int wm   = wid >> 2, wn = wid & 3;
    const int m0   = blockIdx.y * 128, n0 = blockIdx.x * 128;

    const int ar0 = t >> 2,  akc = (t & 3) * 4;
    const int bk0 = t >> 5,  bcc = (t & 31) * 4;

    float acc[4][4][4];
#pragma unroll
    for (int i = 0; i < 4; i++)
#pragma unroll
        for (int j = 0; j < 4; j++)
#pragma unroll
            for (int r = 0; r < 4; r++) acc[i][j][r] = 0.f;

    const int NIT = Kdim >> 4;

#pragma unroll
    for (int s = 0; s < 2; s++) {
        const int k0 = s << 4;
        cp16(&As[s][ar0][akc],      &A[(size_t)(m0 + ar0) * Kdim + k0 + akc]);
        cp16(&As[s][ar0 + 64][akc], &A[(size_t)(m0 + ar0 + 64) * Kdim + k0 + akc]);
        cp16(&Bs[s][bk0][bcc],      &W[(size_t)(k0 + bk0) * Ndim + n0 + bcc]);
        cp16(&Bs[s][bk0 + 8][bcc],  &W[(size_t)(k0 + bk0 + 8) * Ndim + n0 + bcc]);
        CP_COMMIT();
    }

    int sc = 0, sl = 2;
    for (int it = 0; it < NIT; it++) {
        CP_WAIT1();
        __syncthreads();

        if (it + 2 < NIT) {
            const int k0 = (it + 2) << 4;
            cp16(&As[sl][ar0][akc],      &A[(size_t)(m0 + ar0) * Kdim + k0 + akc]);
            cp16(&As[sl][ar0 + 64][akc], &A[(size_t)(m0 + ar0 + 64) * Kdim + k0 + akc]);
            cp16(&Bs[sl][bk0][bcc],      &W[(size_t)(k0 + bk0) * Ndim + n0 + bcc]);
            cp16(&Bs[sl][bk0 + 8][bcc],  &W[(size_t)(k0 + bk0 + 8) * Ndim + n0 + bcc]);
        }
        CP_COMMIT();

#pragma unroll
        for (int ks = 0; ks < 16; ks += 8) {
            uint32_t afrag[4][4];
#pragma unroll
            for (int mf = 0; mf < 4; mf++) {
                const int row = wm * 64 + mf * 16 + g;
                afrag[mf][0] = __float_as_uint(As[sc][row][ks + tg]);
                afrag[mf][1] = __float_as_uint(As[sc][row + 8][ks + tg]);
                afrag[mf][2] = __float_as_uint(As[sc][row][ks + tg + 4]);
                afrag[mf][3] = __float_as_uint(As[sc][row + 8][ks + tg + 4]);
            }
#pragma unroll
            for (int nf = 0; nf < 4; nf++) {
                const int col = wn * 32 + nf * 8 + g;
                const uint32_t b0 = __float_as_uint(Bs[sc][ks + tg][col]);
                const uint32_t b1 = __float_as_uint(Bs[sc][ks + tg + 4][col]);
#pragma unroll
                for (int mf = 0; mf < 4; mf++)
                    mma16n8k8(acc[mf][nf], afrag[mf], b0, b1);
            }
        }
        sc = (sc + 1 == STAGES) ? 0 : sc + 1;
        sl = (sl + 1 == STAGES) ? 0 : sl + 1;
    }

    // epilogue: + bias, optional RoPE, optional tf32 rounding of output
#pragma unroll
    for (int mf = 0; mf < 4; mf++) {
        const int row = m0 + wm * 64 + mf * 16 + g;
#pragma unroll
        for (int nf = 0; nf < 4; nf++) {
            const int col = n0 + wn * 32 + nf * 8 + 2 * tg;
            const float bx = bias[col], by = bias[col + 1];
            float x0 = acc[mf][nf][0] + bx, x1 = acc[mf][nf][1] + by;
            float y0 = acc[mf][nf][2] + bx, y1 = acc[mf][nf][3] + by;
            if (do_rope) {
                const int i = (col & 63) >> 1;
                const float inv = exp2f(-13.287712379549449f * (float)i
                                        * (1.0f / 32.0f));
                float s0, c0, s1, c1;
                sincosf((float)(row & (SS - 1)) * inv, &s0, &c0);
                sincosf((float)((row + 8) & (SS - 1)) * inv, &s1, &c1);
                const float r0 = x0 * c0 - x1 * s0, r1 = x0 * s0 + x1 * c0;
                const float r2 = y0 * c1 - y1 * s1, r3 = y0 * s1 + y1 * c1;
                x0 = r0; x1 = r1; y0 = r2; y1 = r3;
            }
            if (round_out) {
                x0 = __uint_as_float(f2tf(x0)); x1 = __uint_as_float(f2tf(x1));
                y0 = __uint_as_float(f2tf(y0)); y1 = __uint_as_float(f2tf(y1));
            }
            *(float2*)&C[(size_t)row * Ndim + col]       = make_float2(x0, x1);
            *(float2*)&C[(size_t)(row + 8) * Ndim + col] = make_float2(y0, y1);
        }
    }
}

// ============ fused flash attention (tf32 mma, online softmax) ==============
// K row-major stride 68, V stride 72, QP stride 68: conflict-free frag LDS.
// K/V double-buffered cp.async with 1-tile prefetch.
__global__ __launch_bounds__(256, 2) void flash_kernel()
{
    __shared__ float Ks[2][64][68];    // K tile row-major: [j][d]
    __shared__ float Vs[2][64][72];    // V tile: [j][d]
    __shared__ float QPs[128][68];     // Q tile, then P strips

    const int qt = gridDim.x - 1 - blockIdx.x;   // biggest workloads first
    const int bh = blockIdx.y;
    const int h = bh & (NH - 1), b = bh >> 5, hk = h >> 2;
    const int q0 = qt * BQ;
    const int t = threadIdx.x, w = t >> 5, lane = t & 31;
    const int g = lane >> 2, tg = lane & 3;
    const int r0 = w * 16 + g;

    const float* kbase = g_k + (size_t)b * SS * KVD + hk * 64;
    const float* vbase = g_v + (size_t)b * SS * KVD + hk * 64;

    // ---- stage Q (cp.async) + K/V tile 0 ----
    {
        const float* qbase = g_q + (size_t)(b * SS + q0) * DM + h * 64;
#pragma unroll
        for (int u = 0; u < 8; u++) {
            const int c = t + 256 * u;             // 2048 float4 chunks
            const int r = c >> 4, dc = (c & 15) * 4;
            cp16(&QPs[r][dc], qbase + (size_t)r * DM + dc);
        }
#pragma unroll
        for (int u = 0; u < 4; u++) {
            const int c = t + 256 * u;             // 1024 chunks
            const int r = c >> 4, dc = (c & 15) * 4;
            cp16(&Ks[0][r][dc], kbase + (size_t)r * KVD + dc);
            cp16(&Vs[0][r][dc], vbase + (size_t)r * KVD + dc);
        }
        CP_COMMIT();
        CP_WAIT0();
        __syncthreads();
    }

    uint32_t qf[8][4];
#pragma unroll
    for (int ks = 0; ks < 8; ks++) {
        qf[ks][0] = __float_as_uint(QPs[r0][ks * 8 + tg]);
        qf[ks][1] = __float_as_uint(QPs[r0 + 8][ks * 8 + tg]);
        qf[ks][2] = __float_as_uint(QPs[r0][ks * 8 + tg + 4]);
        qf[ks][3] = __float_as_uint(QPs[r0 + 8][ks * 8 + tg + 4]);
    }

    float o[8][4];
#pragma unroll
    for (int i = 0; i < 8; i++)
#pragma unroll
        for (int j = 0; j < 4; j++) o[i][j] = 0.f;
    float m0v = -INFINITY, m1v = -INFINITY, l0 = 0.f, l1 = 0.f;

    const int njt = 2 * qt + 2;
    for (int jt = 0; jt < njt; jt++) {
        const int bf = jt & 1;
        __syncthreads();                 // all warps done with buffer bf^1

        if (jt + 1 < njt) {              // prefetch next tile into bf^1
            const int jn = (jt + 1) * BJ;
#pragma unroll
            for (int u = 0; u < 4; u++) {
                const int c = t + 256 * u;
                const int r = c >> 4, dc = (c & 15) * 4;
                cp16(&Ks[bf ^ 1][r][dc], kbase + (size_t)(jn + r) * KVD + dc);
                cp16(&Vs[bf ^ 1][r][dc], vbase + (size_t)(jn + r) * KVD + dc);
            }
        }
        CP_COMMIT();
        CP_WAIT1();                      // tile jt's data resident
        __syncthreads();

        // ---- S = Q K^T  (B-operand read from row-major K) ----
        float sf[8][4];
#pragma unroll
        for (int i = 0; i < 8; i++)
#pragma unroll
            for (int j = 0; j < 4; j++) sf[i][j] = 0.f;
#pragma unroll
        for (int ks = 0; ks < 8; ks++)
#pragma unroll
            for (int nf = 0; nf < 8; nf++) {
                const uint32_t b0 = __float_as_uint(Ks[bf][nf * 8 + g][ks * 8 + tg]);
                const uint32_t b1 = __float_as_uint(Ks[bf][nf * 8 + g][ks * 8 + tg + 4]);
                mma16n8k8(sf[nf], qf[ks], b0, b1);
            }

        // ---- causal mask ----
        const int j0 = jt * BJ;
        if (j0 + BJ - 1 > q0 + w * 16) {
            const int ra = q0 + r0, rb = ra + 8;
#pragma unroll
            for (int nf = 0; nf < 8; nf++) {
                const int c = j0 + nf * 8 + 2 * tg;
                if (c     > ra) sf[nf][0] = -INFINITY;
                if (c + 1 > ra) sf[nf][1] = -INFINITY;
                if (c     > rb) sf[nf][2] = -INFINITY;
                if (c + 1 > rb) sf[nf][3] = -INFINITY;
            }
        }

        // ---- online softmax ----
        float rm0 = -INFINITY, rm1 = -INFINITY;
#pragma unroll
        for (int nf = 0; nf < 8; nf++) {
            rm0 = fmaxf(rm0, fmaxf(sf[nf][0], sf[nf][1]));
            rm1 = fmaxf(rm1, fmaxf(sf[nf][2], sf[nf][3]));
        }
        rm0 = fmaxf(rm0, __shfl_xor_sync(0xffffffffu, rm0, 1));
        rm0 = fmaxf(rm0, __shfl_xor_sync(0xffffffffu, rm0, 2));
        rm1 = fmaxf(rm1, __shfl_xor_sync(0xffffffffu, rm1, 1));
        rm1 = fmaxf(rm1, __shfl_xor_sync(0xffffffffu, rm1, 2));

        const float mn0 = fmaxf(m0v, 0.125f * rm0);
        const float mn1 = fmaxf(m1v, 0.125f * rm1);
        const float a0 = __expf(m0v - mn0);
        const float a1 = __expf(m1v - mn1);
        m0v = mn0; m1v = mn1;

        float rs0 = 0.f, rs1 = 0.f;
#pragma unroll
        for (int nf = 0; nf < 8; nf++) {
            sf[nf][0] = __expf(fmaf(sf[nf][0], 0.125f, -mn0));
            sf[nf][1] = __expf(fmaf(sf[nf][1], 0.125f, -mn0));
            sf[nf][2] = __expf(fmaf(sf[nf][2], 0.125f, -mn1));
            sf[nf][3] = __expf(fmaf(sf[nf][3], 0.125f, -mn1));
            rs0 += sf[nf][0] + sf[nf][1];
            rs1 += sf[nf][2] + sf[nf][3];
        }
        rs0 += __shfl_xor_sync(0xffffffffu, rs0, 1);
        rs0 += __shfl_xor_sync(0xffffffffu, rs0, 2);
        rs1 += __shfl_xor_sync(0xffffffffu, rs1, 1);
        rs1 += __shfl_xor_sync(0xffffffffu, rs1, 2);
        l0 = l0 * a0 + rs0;
        l1 = l1 * a1 + rs1;

#pragma unroll
        for (int dn = 0; dn < 8; dn++) {
            o[dn][0] *= a0; o[dn][1] *= a0;
            o[dn][2] *= a1; o[dn][3] *= a1;
        }

        // ---- P -> SMEM (own strip, 64-bit stores) ----
#pragma unroll
        for (int nf = 0; nf < 8; nf++) {
            const int c = nf * 8 + 2 * tg;
            *(uint2*)&QPs[r0][c]     = make_uint2(f2tf(sf[nf][0]), f2tf(sf[nf][1]));
            *(uint2*)&QPs[r0 + 8][c] = make_uint2(f2tf(sf[nf][2]), f2tf(sf[nf][3]));
        }
        __syncwarp();

        // ---- O += P V ----
#pragma unroll
        for (int kb = 0; kb < 8; kb++) {
            uint32_t pa[4];
            pa[0] = __float_as_uint(QPs[r0][kb * 8 + tg]);
            pa[1] = __float_as_uint(QPs[r0 + 8][kb * 8 + tg]);
            pa[2] = __float_as_uint(QPs[r0][kb * 8 + tg + 4]);
            pa[3] = __float_as_uint(QPs[r0 + 8][kb * 8 + tg + 4]);
#pragma unroll
            for (int dn = 0; dn < 8; dn++) {
                const uint32_t b0 = __float_as_uint(Vs[bf][kb * 8 + tg][dn * 8 + g]);
                const uint32_t b1 = __float_as_uint(Vs[bf][kb * 8 + tg + 4][dn * 8 + g]);
                mma16n8k8(o[dn], pa, b0, b1);
            }
        }
    }

    // ---- epilogue: normalize, round to tf32 (feeds O-proj), write ----
    const float il0 = 1.0f / l0, il1 = 1.0f / l1;
    const size_t ra = (size_t)(b * SS + q0 + r0) * DM + h * 64;
    const size_t rb = ra + (size_t)8 * DM;
#pragma unroll
    for (int dn = 0; dn < 8; dn++) {
        const int c = dn * 8 + 2 * tg;
        *(uint2*)&g_attn[ra + c] = make_uint2(f2tf(o[dn][0] * il0), f2tf(o[dn][1] * il0));
        *(uint2*)&g_attn[rb + c] = make_uint2(f2tf(o[dn][2] * il1), f2tf(o[dn][3] * il1));
    }
}

// ---------------- launch ----------------------------------------------------
extern "C" void kernel_launch(void* const* d_in, const int* in_sizes, int n_in,
                              void* d_out, int out_size)
{
    const float* x  = (const float*)d_in[0];
    const float* Wq = (const float*)d_in[1];
    const float* bq = (const float*)d_in[2];
    const float* Wk = (const float*)d_in[3];
    const float* bk = (const float*)d_in[4];
    const float* Wv = (const float*)d_in[5];
    const float* bv = (const float*)d_in[6];
    const float* Wo = (const float*)d_in[7];
    const float* bo = (const float*)d_in[8];
    float* out = (float*)d_out;

    float *q, *k, *v, *attn, *xr, *wq, *wk, *wv, *wo;
    cudaGetSymbolAddress((void**)&q,    g_q);
    cudaGetSymbolAddress((void**)&k,    g_k);
    cudaGetSymbolAddress((void**)&v,    g_v);
    cudaGetSymbolAddress((void**)&attn, g_attn);
    cudaGetSymbolAddress((void**)&xr,   g_xr);
    cudaGetSymbolAddress((void**)&wq,   g_wq);
    cudaGetSymbolAddress((void**)&wk,   g_wk);
    cudaGetSymbolAddress((void**)&wv,   g_wv);
    cudaGetSymbolAddress((void**)&wo,   g_wo);

    // pre-round inputs to tf32 (removes CVTs from all GEMM inner loops)
    tf32_round_kernel<<<(MTOK * DM / 4 + 255) / 256, 256>>>(x, xr, MTOK * DM / 4);
    tf32_round_kernel<<<(DM * DM / 4 + 255) / 256, 256>>>(Wq, wq, DM * DM / 4);
    tf32_round_kernel<<<(DM * KVD / 4 + 255) / 256, 256>>>(Wk, wk, DM * KVD / 4);
    tf32_round_kernel<<<(DM * KVD / 4 + 255) / 256, 256>>>(Wv, wv, DM * KVD / 4);
    tf32_round_kernel<<<(DM * DM / 4 + 255) / 256, 256>>>(Wo, wo, DM * DM / 4);

    // Q/K/V projections (RoPE fused into Q/K epilogues; outputs tf32-rounded)
    sgemm_mma<<<dim3(DM / 128, MTOK / 128), 256>>>(xr, wq, bq, q, DM, DM, 1, 1);
    sgemm_mma<<<dim3(KVD / 128, MTOK / 128), 256>>>(xr, wk, bk, k, KVD, DM, 1, 1);
    sgemm_mma<<<dim3(KVD / 128, MTOK / 128), 256>>>(xr, wv, bv, v, KVD, DM, 0, 1);

    // fused attention (emits tf32-rounded attn)
    flash_kernel<<<dim3(SS / BQ, BB * NH), 256>>>();

    // output projection (full-precision fp32 output)
    sgemm_mma<<<dim3(DM / 128, MTOK / 128), 256>>>(attn, wo, bo, out, DM, DM, 0, 0);
}

// round 9
// speedup vs baseline: 5.2911x; 1.2451x over previous
#include <cuda_runtime.h>
#include <cstdint>
#include <math.h>

#define BB   2
#define SS   1024
#define DM   2048
#define NH   32
#define NKV  8
#define DK   64
#define MTOK (BB * SS)          // 2048 tokens
#define KVD  (NKV * DK)         // 512
#define BQ   128
#define BJ   64
#define STAGES 3

// ---------------- scratch (device globals: no allocations allowed) ----------
__device__ float g_q[(size_t)MTOK * DM];
__device__ float g_k[(size_t)MTOK * KVD];
__device__ float g_v[(size_t)MTOK * KVD];
__device__ float g_attn[(size_t)MTOK * DM];
__device__ float g_xr[(size_t)MTOK * DM];    // tf32-rounded x
__device__ float g_wq[(size_t)DM * DM];
__device__ float g_wk[(size_t)DM * KVD];
__device__ float g_wv[(size_t)DM * KVD];
__device__ float g_wo[(size_t)DM * DM];

// ---------------- helpers ---------------------------------------------------
__device__ __forceinline__ uint32_t f2tf(float f) {
    uint32_t r;
    asm("cvt.rna.tf32.f32 %0, %1;" : "=r"(r) : "f"(f));
    return r;
}
__device__ __forceinline__ void mma16n8k8(float* c, const uint32_t* a,
                                          uint32_t b0, uint32_t b1) {
    asm volatile(
        "mma.sync.aligned.m16n8k8.row.col.f32.tf32.tf32.f32 "
        "{%0,%1,%2,%3}, {%4,%5,%6,%7}, {%8,%9}, {%0,%1,%2,%3};"
        : "+f"(c[0]), "+f"(c[1]), "+f"(c[2]), "+f"(c[3])
        : "r"(a[0]), "r"(a[1]), "r"(a[2]), "r"(a[3]), "r"(b0), "r"(b1));
}
__device__ __forceinline__ void ldsm4(uint32_t* r, uint32_t saddr) {
    asm volatile("ldmatrix.sync.aligned.m8n8.x4.shared.b16 {%0,%1,%2,%3}, [%4];"
        : "=r"(r[0]), "=r"(r[1]), "=r"(r[2]), "=r"(r[3]) : "r"(saddr));
}
__device__ __forceinline__ void cp16(void* smem, const void* g) {
    uint32_t s = (uint32_t)__cvta_generic_to_shared(smem);
    asm volatile("cp.async.cg.shared.global [%0], [%1], 16;" :: "r"(s), "l"(g));
}
#define CP_COMMIT() asm volatile("cp.async.commit_group;" ::: "memory")
#define CP_WAIT1()  asm volatile("cp.async.wait_group 1;" ::: "memory")
#define CP_WAIT0()  asm volatile("cp.async.wait_group 0;" ::: "memory")

// ---------------- tf32 pre-round (elementwise, float4) ----------------------
__global__ __launch_bounds__(256) void tf32_round_kernel(
    const float* __restrict__ s, float* __restrict__ d, int n4)
{
    const int i = blockIdx.x * blockDim.x + threadIdx.x;
    if (i >= n4) return;
    float4 v = ((const float4*)s)[i];
    ((uint4*)d)[i] = make_uint4(f2tf(v.x), f2tf(v.y), f2tf(v.z), f2tf(v.w));
}

// ==== tf32 GEMM core (pre-rounded inputs): C = A @ W + bias =================
// 128x128 CTA tile, BK=16, 256 threads, 8 warps (2m x 4n), 3-stage cp.async,
// A-fragments via ldmatrix.x4.
__device__ __forceinline__ void gemm_core(
    const float* __restrict__ A, const float* __restrict__ W,
    const float* __restrict__ bias, float* __restrict__ C,
    int Ndim, int Kdim, int m0, int n0, int do_rope, int round_out)
{
    __shared__ float As[STAGES][128][20];
    __shared__ float Bs[STAGES][16][136];

    const int t    = threadIdx.x;
    const int wid  = t >> 5, lane = t & 31;
    const int g    = lane >> 2, tg = lane & 3;
    const int wm   = wid >> 2, wn = wid & 3;

    const int ar0 = t >> 2,  akc = (t & 3) * 4;
    const int bk0 = t >> 5,  bcc = (t & 31) * 4;

    // ldmatrix lane addressing: row = mbase + (lane&15), col = ks + (lane>>4)*4
    const int lrow = lane & 15, lcol = (lane >> 4) * 4;
    const uint32_t a_sbase = (uint32_t)__cvta_generic_to_shared(&As[0][0][0]);

    float acc[4][4][4];
#pragma unroll
    for (int i = 0; i < 4; i++)
#pragma unroll
        for (int j = 0; j < 4; j++)
#pragma unroll
            for (int r = 0; r < 4; r++) acc[i][j][r] = 0.f;

    const int NIT = Kdim >> 4;

#pragma unroll
    for (int s = 0; s < 2; s++) {
        const int k0 = s << 4;
        cp16(&As[s][ar0][akc],      &A[(size_t)(m0 + ar0) * Kdim + k0 + akc]);
        cp16(&As[s][ar0 + 64][akc], &A[(size_t)(m0 + ar0 + 64) * Kdim + k0 + akc]);
        cp16(&Bs[s][bk0][bcc],      &W[(size_t)(k0 + bk0) * Ndim + n0 + bcc]);
        cp16(&Bs[s][bk0 + 8][bcc],  &W[(size_t)(k0 + bk0 + 8) * Ndim + n0 + bcc]);
        CP_COMMIT();
    }

    int sc = 0, sl = 2;
    for (int it = 0; it < NIT; it++) {
        CP_WAIT1();
        __syncthreads();

        if (it + 2 < NIT) {
            const int k0 = (it + 2) << 4;
            cp16(&As[sl][ar0][akc],      &A[(size_t)(m0 + ar0) * Kdim + k0 + akc]);
            cp16(&As[sl][ar0 + 64][akc], &A[(size_t)(m0 + ar0 + 64) * Kdim + k0 + akc]);
            cp16(&Bs[sl][bk0][bcc],      &W[(size_t)(k0 + bk0) * Ndim + n0 + bcc]);
            cp16(&Bs[sl][bk0 + 8][bcc],  &W[(size_t)(k0 + bk0 + 8) * Ndim + n0 + bcc]);
        }
        CP_COMMIT();

        const uint32_t a_stage = a_sbase + (uint32_t)sc * sizeof(As[0]);
#pragma unroll
        for (int ks = 0; ks < 16; ks += 8) {
            uint32_t afrag[4][4];
#pragma unroll
            for (int mf = 0; mf < 4; mf++) {
                const int row = wm * 64 + mf * 16 + lrow;
                ldsm4(afrag[mf], a_stage + (uint32_t)(row * 20 + ks + lcol) * 4);
            }
#pragma unroll
            for (int nf = 0; nf < 4; nf++) {
                const int col = wn * 32 + nf * 8 + g;
                const uint32_t b0 = __float_as_uint(Bs[sc][ks + tg][col]);
                const uint32_t b1 = __float_as_uint(Bs[sc][ks + tg + 4][col]);
#pragma unroll
                for (int mf = 0; mf < 4; mf++)
                    mma16n8k8(acc[mf][nf], afrag[mf], b0, b1);
            }
        }
        sc = (sc + 1 == STAGES) ? 0 : sc + 1;
        sl = (sl + 1 == STAGES) ? 0 : sl + 1;
    }

    // epilogue: + bias, optional RoPE, optional tf32 rounding of output
#pragma unroll
    for (int mf = 0; mf < 4; mf++) {
        const int row = m0 + wm * 64 + mf * 16 + g;
#pragma unroll
        for (int nf = 0; nf < 4; nf++) {
            const int col = n0 + wn * 32 + nf * 8 + 2 * tg;
            const float bx = bias[col], by = bias[col + 1];
            float x0 = acc[mf][nf][0] + bx, x1 = acc[mf][nf][1] + by;
            float y0 = acc[mf][nf][2] + bx, y1 = acc[mf][nf][3] + by;
            if (do_rope) {
                const int i = (col & 63) >> 1;
                const float inv = exp2f(-13.287712379549449f * (float)i
                                        * (1.0f / 32.0f));
                float s0, c0, s1, c1;
                sincosf((float)(row & (SS - 1)) * inv, &s0, &c0);
                sincosf((float)((row + 8) & (SS - 1)) * inv, &s1, &c1);
                const float r0 = x0 * c0 - x1 * s0, r1 = x0 * s0 + x1 * c0;
                const float r2 = y0 * c1 - y1 * s1, r3 = y0 * s1 + y1 * c1;
                x0 = r0; x1 = r1; y0 = r2; y1 = r3;
            }
            if (round_out) {
                x0 = __uint_as_float(f2tf(x0)); x1 = __uint_as_float(f2tf(x1));
                y0 = __uint_as_float(f2tf(y0)); y1 = __uint_as_float(f2tf(y1));
            }
            *(float2*)&C[(size_t)row * Ndim + col]       = make_float2(x0, x1);
            *(float2*)&C[(size_t)(row + 8) * Ndim + col] = make_float2(y0, y1);
        }
    }
}

// merged QKV projection: grid.x = 24 (0-15 Q, 16-19 K, 20-23 V)
__global__ __launch_bounds__(256) void sgemm_qkv(
    const float* __restrict__ A,
    const float* __restrict__ wq, const float* __restrict__ bq,
    const float* __restrict__ wk, const float* __restrict__ bk,
    const float* __restrict__ wv, const float* __restrict__ bv,
    float* __restrict__ q, float* __restrict__ k, float* __restrict__ v)
{
    const int nx = blockIdx.x, m0 = blockIdx.y * 128;
    if (nx < 16)
        gemm_core(A, wq, bq, q, DM, DM, m0, nx * 128, 1, 1);
    else if (nx < 20)
        gemm_core(A, wk, bk, k, KVD, DM, m0, (nx - 16) * 128, 1, 1);
    else
        gemm_core(A, wv, bv, v, KVD, DM, m0, (nx - 20) * 128, 0, 1);
}

// generic single GEMM (output projection)
__global__ __launch_bounds__(256) void sgemm_mma(
    const float* __restrict__ A, const float* __restrict__ W,
    const float* __restrict__ bias, float* __restrict__ C,
    int Ndim, int Kdim, int do_rope, int round_out)
{
    gemm_core(A, W, bias, C, Ndim, Kdim, blockIdx.y * 128, blockIdx.x * 128,
              do_rope, round_out);
}

// ============ fused flash attention (tf32 mma, online softmax) ==============
__global__ __launch_bounds__(256, 2) void flash_kernel()
{
    __shared__ float Ks[2][64][68];    // K tile row-major: [j][d]
    __shared__ float Vs[2][64][72];    // V tile: [j][d]
    __shared__ float QPs[128][68];     // Q tile, then P strips

    const int qt = gridDim.x - 1 - blockIdx.x;   // biggest workloads first
    const int bh = blockIdx.y;
    const int h = bh & (NH - 1), b = bh >> 5, hk = h >> 2;
    const int q0 = qt * BQ;
    const int t = threadIdx.x, w = t >> 5, lane = t & 31;
    const int g = lane >> 2, tg = lane & 3;
    const int r0 = w * 16 + g;

    const float* kbase = g_k + (size_t)b * SS * KVD + hk * 64;
    const float* vbase = g_v + (size_t)b * SS * KVD + hk * 64;

    {
        const float* qbase = g_q + (size_t)(b * SS + q0) * DM + h * 64;
#pragma unroll
        for (int u = 0; u < 8; u++) {
            const int c = t + 256 * u;
            const int r = c >> 4, dc = (c & 15) * 4;
            cp16(&QPs[r][dc], qbase + (size_t)r * DM + dc);
        }
#pragma unroll
        for (int u = 0; u < 4; u++) {
            const int c = t + 256 * u;
            const int r = c >> 4, dc = (c & 15) * 4;
            cp16(&Ks[0][r][dc], kbase + (size_t)r * KVD + dc);
            cp16(&Vs[0][r][dc], vbase + (size_t)r * KVD + dc);
        }
        CP_COMMIT();
        CP_WAIT0();
        __syncthreads();
    }

    uint32_t qf[8][4];
#pragma unroll
    for (int ks = 0; ks < 8; ks++) {
        qf[ks][0] = __float_as_uint(QPs[r0][ks * 8 + tg]);
        qf[ks][1] = __float_as_uint(QPs[r0 + 8][ks * 8 + tg]);
        qf[ks][2] = __float_as_uint(QPs[r0][ks * 8 + tg + 4]);
        qf[ks][3] = __float_as_uint(QPs[r0 + 8][ks * 8 + tg + 4]);
    }

    float o[8][4];
#pragma unroll
    for (int i = 0; i < 8; i++)
#pragma unroll
        for (int j = 0; j < 4; j++) o[i][j] = 0.f;
    float m0v = -INFINITY, m1v = -INFINITY, l0 = 0.f, l1 = 0.f;

    const int njt = 2 * qt + 2;
    for (int jt = 0; jt < njt; jt++) {
        const int bf = jt & 1;
        __syncthreads();

        if (jt + 1 < njt) {
            const int jn = (jt + 1) * BJ;
#pragma unroll
            for (int u = 0; u < 4; u++) {
                const int c = t + 256 * u;
                const int r = c >> 4, dc = (c & 15) * 4;
                cp16(&Ks[bf ^ 1][r][dc], kbase + (size_t)(jn + r) * KVD + dc);
                cp16(&Vs[bf ^ 1][r][dc], vbase + (size_t)(jn + r) * KVD + dc);
            }
        }
        CP_COMMIT();
        CP_WAIT1();
        __syncthreads();

        float sf[8][4];
#pragma unroll
        for (int i = 0; i < 8; i++)
#pragma unroll
            for (int j = 0; j < 4; j++) sf[i][j] = 0.f;
#pragma unroll
        for (int ks = 0; ks < 8; ks++)
#pragma unroll
            for (int nf = 0; nf < 8; nf++) {
                const uint32_t b0 = __float_as_uint(Ks[bf][nf * 8 + g][ks * 8 + tg]);
                const uint32_t b1 = __float_as_uint(Ks[bf][nf * 8 + g][ks * 8 + tg + 4]);
                mma16n8k8(sf[nf], qf[ks], b0, b1);
            }

        const int j0 = jt * BJ;
        if (j0 + BJ - 1 > q0 + w * 16) {
            const int ra = q0 + r0, rb = ra + 8;
#pragma unroll
            for (int nf = 0; nf < 8; nf++) {
                const int c = j0 + nf * 8 + 2 * tg;
                if (c     > ra) sf[nf][0] = -INFINITY;
                if (c + 1 > ra) sf[nf][1] = -INFINITY;
                if (c     > rb) sf[nf][2] = -INFINITY;
                if (c + 1 > rb) sf[nf][3] = -INFINITY;
            }
        }

        float rm0 = -INFINITY, rm1 = -INFINITY;
#pragma unroll
        for (int nf = 0; nf < 8; nf++) {
            rm0 = fmaxf(rm0, fmaxf(sf[nf][0], sf[nf][1]));
            rm1 = fmaxf(rm1, fmaxf(sf[nf][2], sf[nf][3]));
        }
        rm0 = fmaxf(rm0, __shfl_xor_sync(0xffffffffu, rm0, 1));
        rm0 = fmaxf(rm0, __shfl_xor_sync(0xffffffffu, rm0, 2));
        rm1 = fmaxf(rm1, __shfl_xor_sync(0xffffffffu, rm1, 1));
        rm1 = fmaxf(rm1, __shfl_xor_sync(0xffffffffu, rm1, 2));

        const float mn0 = fmaxf(m0v, 0.125f * rm0);
        const float mn1 = fmaxf(m1v, 0.125f * rm1);
        const float a0 = __expf(m0v - mn0);
        const float a1 = __expf(m1v - mn1);
        m0v = mn0; m1v = mn1;

        float rs0 = 0.f, rs1 = 0.f;
#pragma unroll
        for (int nf = 0; nf < 8; nf++) {
            sf[nf][0] = __expf(fmaf(sf[nf][0], 0.125f, -mn0));
            sf[nf][1] = __expf(fmaf(sf[nf][1], 0.125f, -mn0));
            sf[nf][2] = __expf(fmaf(sf[nf][2], 0.125f, -mn1));
            sf[nf][3] = __expf(fmaf(sf[nf][3], 0.125f, -mn1));
            rs0 += sf[nf][0] + sf[nf][1];
            rs1 += sf[nf][2] + sf[nf][3];
        }
        rs0 += __shfl_xor_sync(0xffffffffu, rs0, 1);
        rs0 += __shfl_xor_sync(0xffffffffu, rs0, 2);
        rs1 += __shfl_xor_sync(0xffffffffu, rs1, 1);
        rs1 += __shfl_xor_sync(0xffffffffu, rs1, 2);
        l0 = l0 * a0 + rs0;
        l1 = l1 * a1 + rs1;

#pragma unroll
        for (int dn = 0; dn < 8; dn++) {
            o[dn][0] *= a0; o[dn][1] *= a0;
            o[dn][2] *= a1; o[dn][3] *= a1;
        }

#pragma unroll
        for (int nf = 0; nf < 8; nf++) {
            const int c = nf * 8 + 2 * tg;
            *(uint2*)&QPs[r0][c]     = make_uint2(f2tf(sf[nf][0]), f2tf(sf[nf][1]));
            *(uint2*)&QPs[r0 + 8][c] = make_uint2(f2tf(sf[nf][2]), f2tf(sf[nf][3]));
        }
        __syncwarp();

#pragma unroll
        for (int kb = 0; kb < 8; kb++) {
            uint32_t pa[4];
            pa[0] = __float_as_uint(QPs[r0][kb * 8 + tg]);
            pa[1] = __float_as_uint(QPs[r0 + 8][kb * 8 + tg]);
            pa[2] = __float_as_uint(QPs[r0][kb * 8 + tg + 4]);
            pa[3] = __float_as_uint(QPs[r0 + 8][kb * 8 + tg + 4]);
#pragma unroll
            for (int dn = 0; dn < 8; dn++) {
                const uint32_t b0 = __float_as_uint(Vs[bf][kb * 8 + tg][dn * 8 + g]);
                const uint32_t b1 = __float_as_uint(Vs[bf][kb * 8 + tg + 4][dn * 8 + g]);
                mma16n8k8(o[dn], pa, b0, b1);
            }
        }
    }

    const float il0 = 1.0f / l0, il1 = 1.0f / l1;
    const size_t ra = (size_t)(b * SS + q0 + r0) * DM + h * 64;
    const size_t rb = ra + (size_t)8 * DM;
#pragma unroll
    for (int dn = 0; dn < 8; dn++) {
        const int c = dn * 8 + 2 * tg;
        *(uint2*)&g_attn[ra + c] = make_uint2(f2tf(o[dn][0] * il0), f2tf(o[dn][1] * il0));
        *(uint2*)&g_attn[rb + c] = make_uint2(f2tf(o[dn][2] * il1), f2tf(o[dn][3] * il1));
    }
}

// ---------------- launch ----------------------------------------------------
extern "C" void kernel_launch(void* const* d_in, const int* in_sizes, int n_in,
                              void* d_out, int out_size)
{
    const float* x  = (const float*)d_in[0];
    const float* Wq = (const float*)d_in[1];
    const float* bq = (const float*)d_in[2];
    const float* Wk = (const float*)d_in[3];
    const float* bk = (const float*)d_in[4];
    const float* Wv = (const float*)d_in[5];
    const float* bv = (const float*)d_in[6];
    const float* Wo = (const float*)d_in[7];
    const float* bo = (const float*)d_in[8];
    float* out = (float*)d_out;

    float *q, *k, *v, *attn, *xr, *wq, *wk, *wv, *wo;
    cudaGetSymbolAddress((void**)&q,    g_q);
    cudaGetSymbolAddress((void**)&k,    g_k);
    cudaGetSymbolAddress((void**)&v,    g_v);
    cudaGetSymbolAddress((void**)&attn, g_attn);
    cudaGetSymbolAddress((void**)&xr,   g_xr);
    cudaGetSymbolAddress((void**)&wq,   g_wq);
    cudaGetSymbolAddress((void**)&wk,   g_wk);
    cudaGetSymbolAddress((void**)&wv,   g_wv);
    cudaGetSymbolAddress((void**)&wo,   g_wo);

    // pre-round inputs to tf32
    tf32_round_kernel<<<(MTOK * DM / 4 + 255) / 256, 256>>>(x, xr, MTOK * DM / 4);
    tf32_round_kernel<<<(DM * DM / 4 + 255) / 256, 256>>>(Wq, wq, DM * DM / 4);
    tf32_round_kernel<<<(DM * KVD / 4 + 255) / 256, 256>>>(Wk, wk, DM * KVD / 4);
    tf32_round_kernel<<<(DM * KVD / 4 + 255) / 256, 256>>>(Wv, wv, DM * KVD / 4);
    tf32_round_kernel<<<(DM * DM / 4 + 255) / 256, 256>>>(Wo, wo, DM * DM / 4);

    // merged Q/K/V projections (RoPE fused into Q/K epilogues)
    sgemm_qkv<<<dim3(24, MTOK / 128), 256>>>(xr, wq, bq, wk, bk, wv, bv, q, k, v);

    // fused attention (emits tf32-rounded attn)
    flash_kernel<<<dim3(SS / BQ, BB * NH), 256>>>();

    // output projection (full-precision fp32 output)
    sgemm_mma<<<dim3(DM / 128, MTOK / 128), 256>>>(attn, wo, bo, out, DM, DM, 0, 0);
}